// round 5
// baseline (speedup 1.0000x reference)
#include <cuda_runtime.h>
#include <cuda_bf16.h>
#include <cstdint>

// Problem constants
#define BB 2
#define LL 2048
#define DD 1024
#define HH 16
#define HD 64
#define NQKV 3072        // 3*H*HD
#define MROWS (BB*LL)    // 4096

// ---------------- scratch (device globals; no allocations allowed) -------
__device__ float g_qkv[MROWS * NQKV];             // [B*L, 3072] fp32

// split-bf16 operand buffers
__device__ __nv_bfloat16 g_xh[MROWS * DD];
__device__ __nv_bfloat16 g_xl[MROWS * DD];
__device__ __nv_bfloat16 g_wqkvT_h[NQKV * DD];    // [N][K]
__device__ __nv_bfloat16 g_wqkvT_l[NQKV * DD];
__device__ __nv_bfloat16 g_woutT_h[DD * DD];      // [N][K]
__device__ __nv_bfloat16 g_woutT_l[DD * DD];

// attention operands/results, split bf16, [B,H,L,HD] (Q scaled by 0.125*log2e)
__device__ __nv_bfloat16 g_Qh[BB * HH * LL * HD];
__device__ __nv_bfloat16 g_Ql[BB * HH * LL * HD];
__device__ __nv_bfloat16 g_Kh[BB * HH * LL * HD];
__device__ __nv_bfloat16 g_Kl[BB * HH * LL * HD];
__device__ __nv_bfloat16 g_Vh[BB * HH * LL * HD];
__device__ __nv_bfloat16 g_Vl[BB * HH * LL * HD];
__device__ __nv_bfloat16 g_atth[MROWS * DD];      // [B*L, 1024]
__device__ __nv_bfloat16 g_attl[MROWS * DD];

// ==================== helpers =============================================
__device__ __forceinline__ uint32_t smem_u32(const void* p) {
    uint32_t a;
    asm("{ .reg .u64 t; cvta.to.shared.u64 t, %1; cvt.u32.u64 %0, t; }"
        : "=r"(a) : "l"(p));
    return a;
}

__device__ __forceinline__ void split1(float v, __nv_bfloat16& hi, __nv_bfloat16& lo) {
    hi = __float2bfloat16(v);
    lo = __float2bfloat16(v - __bfloat162float(hi));
}

__device__ __forceinline__ uint32_t packbf(float lo, float hi) {
    uint32_t r;
    asm("cvt.rn.bf16x2.f32 %0, %1, %2;" : "=r"(r) : "f"(hi), "f"(lo));
    return r;
}

__device__ __forceinline__ void split_pack(float a, float b, uint32_t& hi, uint32_t& lo) {
    __nv_bfloat16 ah = __float2bfloat16(a), bh = __float2bfloat16(b);
    hi = (uint32_t)__bfloat16_as_ushort(ah) | ((uint32_t)__bfloat16_as_ushort(bh) << 16);
    lo = packbf(a - __bfloat162float(ah), b - __bfloat162float(bh));
}

__device__ __forceinline__ void ldsm4(uint32_t* r, uint32_t addr) {
    asm volatile("ldmatrix.sync.aligned.m8n8.x4.shared.b16 {%0,%1,%2,%3}, [%4];"
                 : "=r"(r[0]), "=r"(r[1]), "=r"(r[2]), "=r"(r[3]) : "r"(addr));
}

__device__ __forceinline__ void ldsm4t(uint32_t* r, uint32_t addr) {
    asm volatile("ldmatrix.sync.aligned.m8n8.x4.trans.shared.b16 {%0,%1,%2,%3}, [%4];"
                 : "=r"(r[0]), "=r"(r[1]), "=r"(r[2]), "=r"(r[3]) : "r"(addr));
}

__device__ __forceinline__ void mma_bf16(float* d, const uint32_t* a, uint32_t b0, uint32_t b1) {
    asm volatile(
        "mma.sync.aligned.m16n8k16.row.col.f32.bf16.bf16.f32 "
        "{%0,%1,%2,%3}, {%4,%5,%6,%7}, {%8,%9}, {%0,%1,%2,%3};"
        : "+f"(d[0]), "+f"(d[1]), "+f"(d[2]), "+f"(d[3])
        : "r"(a[0]), "r"(a[1]), "r"(a[2]), "r"(a[3]), "r"(b0), "r"(b1));
}

__device__ __forceinline__ void cpa16(uint32_t dst, const void* src) {
    asm volatile("cp.async.cg.shared.global [%0], [%1], 16;" :: "r"(dst), "l"(src));
}
#define CP_COMMIT() asm volatile("cp.async.commit_group;" ::: "memory")
#define CP_WAIT0()  asm volatile("cp.async.wait_group 0;" ::: "memory")
#define CP_WAIT1()  asm volatile("cp.async.wait_group 1;" ::: "memory")

// fast exp2 on FMA pipe (x <= 0 expected; clamped at -120)
__device__ __forceinline__ float fexp2(float x) {
    x = fmaxf(x, -120.0f);
    float n = floorf(x);
    float f = x - n;
    float p = 1.5404226e-4f;
    p = fmaf(p, f, 1.3333558e-3f);
    p = fmaf(p, f, 9.6181291e-3f);
    p = fmaf(p, f, 5.5504109e-2f);
    p = fmaf(p, f, 2.4022651e-1f);
    p = fmaf(p, f, 6.9314718e-1f);
    p = fmaf(p, f, 1.0f);
    return __int_as_float(__float_as_int(p) + (((int)n) << 23));
}

// ==================== conversion kernels ==================================
__global__ void conv_split(const float* __restrict__ src,
                           __nv_bfloat16* __restrict__ hi,
                           __nv_bfloat16* __restrict__ lo, int n4)
{
    const int i = blockIdx.x * blockDim.x + threadIdx.x;
    if (i >= n4) return;
    float4 v = ((const float4*)src)[i];
    __nv_bfloat16 h[4], l[4];
    split1(v.x, h[0], l[0]);
    split1(v.y, h[1], l[1]);
    split1(v.z, h[2], l[2]);
    split1(v.w, h[3], l[3]);
    ((uint2*)hi)[i] = *(uint2*)h;
    ((uint2*)lo)[i] = *(uint2*)l;
}

__global__ void conv_splitT(const float* __restrict__ W,
                            __nv_bfloat16* __restrict__ hiT,
                            __nv_bfloat16* __restrict__ loT,
                            int Kdim, int Ndim)
{
    __shared__ float t[32][33];
    const int tx = threadIdx.x, ty = threadIdx.y;
    const int nb = blockIdx.x * 32;
    const int kb = blockIdx.y * 32;
    #pragma unroll
    for (int i = 0; i < 4; i++)
        t[ty + i * 8][tx] = W[(size_t)(kb + ty + i * 8) * Ndim + nb + tx];
    __syncthreads();
    #pragma unroll
    for (int i = 0; i < 4; i++) {
        const float v = t[tx][ty + i * 8];
        __nv_bfloat16 h, l;
        split1(v, h, l);
        const size_t o = (size_t)(nb + ty + i * 8) * Kdim + kb + tx;
        hiT[o] = h;
        loT[o] = l;
    }
}

// ==================== warp-mma split-bf16 GEMM (cp.async 2-stage) =========
#define GBM 128
#define GBN 128
#define GBK 32
#define SROW 20                       // padded row stride (u32) = 80B
#define GOP  (GBM * SROW * 4)         // one operand buffer: 10240 B
// regions (x2 buffers each): AH, AL, BH, BL
#define GAH 0
#define GAL (2 * GOP)
#define GBH (4 * GOP)
#define GBL (6 * GOP)
#define GEMM_SMEM (8 * GOP)           // 81920 B

template <bool BIAS>
__global__ __launch_bounds__(256, 2)
void mma_gemm(const __nv_bfloat16* __restrict__ Ahg, const __nv_bfloat16* __restrict__ Alg,
              const __nv_bfloat16* __restrict__ Bhg, const __nv_bfloat16* __restrict__ Blg,
              const float* __restrict__ bias, float* __restrict__ C,
              int M, int Ntot, int K)
{
    extern __shared__ char gsm[];
    const uint32_t sb = smem_u32(gsm);

    const int tid = threadIdx.x;
    const int wid = tid >> 5;
    const int lane = tid & 31;
    const int warpM = wid & 3;
    const int warpN = wid >> 2;
    const int mBase = blockIdx.y * GBM;
    const int nBase = blockIdx.x * GBN;

    const uint32_t lrow = lane & 15;
    const uint32_t lhi  = (lane >> 4) << 4;

    float acc[2][8][4];
    #pragma unroll
    for (int a = 0; a < 2; a++)
        #pragma unroll
        for (int b = 0; b < 8; b++)
            #pragma unroll
            for (int c2 = 0; c2 < 4; c2++) acc[a][b][c2] = 0.f;

    const int row = tid >> 1;
    const int seg = tid & 1;
    const uint32_t so = (row * SROW + seg * 8) * 4;   // byte offset in buffer
    const int nchunks = K / GBK;

    // staging lambda: chunk c into buffer buf
    auto stage = [&](int c, int buf) {
        const int k0 = c * GBK;
        const size_t ga = (size_t)(mBase + row) * K + k0 + seg * 16;
        const size_t gb = (size_t)(nBase + row) * K + k0 + seg * 16;
        const uint32_t bo = buf * GOP;
        cpa16(sb + GAH + bo + so,      Ahg + ga);
        cpa16(sb + GAH + bo + so + 16, Ahg + ga + 8);
        cpa16(sb + GAL + bo + so,      Alg + ga);
        cpa16(sb + GAL + bo + so + 16, Alg + ga + 8);
        cpa16(sb + GBH + bo + so,      Bhg + gb);
        cpa16(sb + GBH + bo + so + 16, Bhg + gb + 8);
        cpa16(sb + GBL + bo + so,      Blg + gb);
        cpa16(sb + GBL + bo + so + 16, Blg + gb + 8);
    };

    stage(0, 0);
    CP_COMMIT();

    for (int c = 0; c < nchunks; c++) {
        if (c + 1 < nchunks) {
            stage(c + 1, (c + 1) & 1);
            CP_COMMIT();
            CP_WAIT1();
        } else {
            CP_WAIT0();
        }
        __syncthreads();

        const uint32_t bo = (c & 1) * GOP;
        const uint32_t bAh = sb + GAH + bo, bAl = sb + GAL + bo;
        const uint32_t bBh = sb + GBH + bo, bBl = sb + GBL + bo;

        #pragma unroll
        for (int ks = 0; ks < 2; ks++) {
            const uint32_t kboff = ks * 32 + lhi;
            uint32_t ah[2][4], al[2][4];
            #pragma unroll
            for (int mt = 0; mt < 2; mt++) {
                const uint32_t ro = (warpM * 32 + mt * 16 + lrow) * (SROW * 4) + kboff;
                ldsm4(ah[mt], bAh + ro);
                ldsm4(al[mt], bAl + ro);
            }
            #pragma unroll
            for (int reg = 0; reg < 4; reg++) {
                const uint32_t ro = (warpN * 64 + reg * 16 + lrow) * (SROW * 4) + kboff;
                uint32_t bh[4], bl[4];
                ldsm4(bh, bBh + ro);
                ldsm4(bl, bBl + ro);
                #pragma unroll
                for (int mt = 0; mt < 2; mt++) {
                    #pragma unroll
                    for (int t = 0; t < 2; t++) {
                        float* d = acc[mt][reg * 2 + t];
                        mma_bf16(d, ah[mt], bh[t], bh[t + 2]);
                        mma_bf16(d, ah[mt], bl[t], bl[t + 2]);
                        mma_bf16(d, al[mt], bh[t], bh[t + 2]);
                    }
                }
            }
        }
        __syncthreads();
    }

    const int qrow = lane >> 2;
    const int qcol = (lane & 3) * 2;
    #pragma unroll
    for (int mt = 0; mt < 2; mt++) {
        const int m0 = mBase + warpM * 32 + mt * 16 + qrow;
        #pragma unroll
        for (int n8 = 0; n8 < 8; n8++) {
            const int col = nBase + warpN * 64 + n8 * 8 + qcol;
            float2 v0, v1;
            v0.x = acc[mt][n8][0]; v0.y = acc[mt][n8][1];
            v1.x = acc[mt][n8][2]; v1.y = acc[mt][n8][3];
            if (BIAS) {
                const float b0 = bias[col], b1 = bias[col + 1];
                v0.x += b0; v0.y += b1;
                v1.x += b0; v1.y += b1;
            }
            *(float2*)&C[(size_t)m0 * Ntot + col] = v0;
            *(float2*)&C[(size_t)(m0 + 8) * Ntot + col] = v1;
        }
    }
}

// --------------- RoPE + reshape + split to bf16 ---------------------------
__global__ void rope_split(const float* __restrict__ qkv,
                           const float* __restrict__ cosT,
                           const float* __restrict__ sinT,
                           __nv_bfloat16* __restrict__ Qh, __nv_bfloat16* __restrict__ Ql,
                           __nv_bfloat16* __restrict__ Kh, __nv_bfloat16* __restrict__ Kl,
                           __nv_bfloat16* __restrict__ Vh, __nv_bfloat16* __restrict__ Vl)
{
    const int idx = blockIdx.x * blockDim.x + threadIdx.x;
    if (idx >= BB * LL * HH * 32) return;
    const int d = idx & 31;
    const int h = (idx >> 5) & (HH - 1);
    const int l = (idx >> 9) & (LL - 1);
    const int b = idx >> 20;

    const float* row = qkv + ((size_t)(b * LL + l)) * NQKV;
    const float c0 = cosT[l * HD + d],      c1 = cosT[l * HD + d + 32];
    const float s0 = sinT[l * HD + d],      s1 = sinT[l * HD + d + 32];

    const float q0 = row[h * HD + d],            q1 = row[h * HD + d + 32];
    const float k0 = row[DD + h * HD + d],       k1 = row[DD + h * HD + d + 32];
    const float v0 = row[2 * DD + h * HD + d],   v1 = row[2 * DD + h * HD + d + 32];

    const float scale = 0.125f * 1.4426950408889634f;  // HD^-0.5 * log2(e)
    const size_t o = ((size_t)(b * HH + h) * LL + l) * HD;

    __nv_bfloat16 hi, lo;
    split1((q0 * c0 - q1 * s0) * scale, hi, lo); Qh[o + d] = hi;      Ql[o + d] = lo;
    split1((q1 * c1 + q0 * s1) * scale, hi, lo); Qh[o + d + 32] = hi; Ql[o + d + 32] = lo;
    split1(k0 * c0 - k1 * s0, hi, lo);           Kh[o + d] = hi;      Kl[o + d] = lo;
    split1(k1 * c1 + k0 * s1, hi, lo);           Kh[o + d + 32] = hi; Kl[o + d + 32] = lo;
    split1(v0, hi, lo);                          Vh[o + d] = hi;      Vl[o + d] = lo;
    split1(v1, hi, lo);                          Vh[o + d + 32] = hi; Vl[o + d + 32] = lo;
}

// --------------- flash attention (mma.sync, split bf16, cp.async) ---------
#define RSTRIDE 144               // padded smem row (72 bf16)
#define ASQH 0
#define ASQL 18432
#define KVB  36864                // KV double-buffer base
#define KVSZ 36864                // one KV buffer (KH,KL,VH,VL @ 9216 each)
#define KOFF_KL 9216
#define KOFF_VH 18432
#define KOFF_VL 27648
#define ATT_SMEM (KVB + 2 * KVSZ) // 110592

__global__ __launch_bounds__(256, 1)
void flash_attn(const __nv_bfloat16* __restrict__ Qhg, const __nv_bfloat16* __restrict__ Qlg,
                const __nv_bfloat16* __restrict__ Khg, const __nv_bfloat16* __restrict__ Klg,
                const __nv_bfloat16* __restrict__ Vhg, const __nv_bfloat16* __restrict__ Vlg,
                __nv_bfloat16* __restrict__ Oh, __nv_bfloat16* __restrict__ Ol)
{
    extern __shared__ char smem[];
    const uint32_t sb = smem_u32(smem);
    const int tid = threadIdx.x, wid = tid >> 5, lane = tid & 31;
    const int qt = (LL / 128 - 1) - blockIdx.x;     // big tiles first
    const int bh = blockIdx.y;
    const int b = bh >> 4, h = bh & 15;
    const int q0 = qt * 128;
    const size_t base = (size_t)bh * LL * HD;

    const int ntiles = q0 / 64 + 2;

    // KV staging via cp.async: tile t into buffer buf
    const int krow = tid >> 1;                 // reuse layout: 2 iters of 256 -> 512 items
    auto stage_kv = [&](int t, int buf) {
        const int k0 = t * 64;
        const uint32_t bo = KVB + buf * KVSZ;
        #pragma unroll
        for (int j = 0; j < 2; j++) {
            const int item = j * 256 + tid;
            const int row = item >> 3, seg = item & 7;
            const size_t g = base + (size_t)(k0 + row) * HD + seg * 8;
            const uint32_t so = bo + row * RSTRIDE + seg * 16;
            cpa16(sb + so,            Khg + g);
            cpa16(sb + so + KOFF_KL,  Klg + g);
            cpa16(sb + so + KOFF_VH,  Vhg + g);
            cpa16(sb + so + KOFF_VL,  Vlg + g);
        }
    };

    // ---- stage Q tile (hi & lo) + first KV tile ----
    {
        const int row = tid >> 1, seg = tid & 1;
        const size_t g = base + (size_t)(q0 + row) * HD + seg * 32;
        const uint32_t dh = sb + ASQH + row * RSTRIDE + seg * 64;
        const uint32_t dl = sb + ASQL + row * RSTRIDE + seg * 64;
        #pragma unroll
        for (int i = 0; i < 4; i++) {
            cpa16(dh + i * 16, Qhg + g + i * 8);
            cpa16(dl + i * 16, Qlg + g + i * 8);
        }
    }
    stage_kv(0, 0);
    CP_COMMIT();
    CP_WAIT0();
    __syncthreads();

    // ---- Q fragments (persistent) ----
    uint32_t qh[4][4], ql[4][4];
    {
        const uint32_t ro = (wid * 16 + (lane & 15)) * RSTRIDE + ((lane >> 4) << 4);
        #pragma unroll
        for (int ks = 0; ks < 4; ks++) {
            ldsm4(qh[ks], sb + ASQH + ro + ks * 32);
            ldsm4(ql[ks], sb + ASQL + ro + ks * 32);
        }
    }
    __syncthreads();

    float acc_o[8][4];
    #pragma unroll
    for (int j = 0; j < 8; j++)
        #pragma unroll
        for (int e = 0; e < 4; e++) acc_o[j][e] = 0.f;
    float m0 = -1e30f, m1 = -1e30f, l0 = 0.f, l1 = 0.f;

    const int qmin = q0 + wid * 16;
    const int r_lo = qmin + (lane >> 2);

    for (int t = 0; t < ntiles; t++) {
        const int k0 = t * 64;
        if (t + 1 < ntiles) {
            stage_kv(t + 1, (t + 1) & 1);
            CP_COMMIT();
            CP_WAIT1();
        } else {
            CP_WAIT0();
        }
        __syncthreads();

        if (k0 <= qmin + 15) {                     // not fully masked for this warp
            const uint32_t kb = sb + KVB + (t & 1) * KVSZ;

            // ---- S = Q·Kᵀ ----
            float s[8][4];
            #pragma unroll
            for (int j = 0; j < 8; j++)
                #pragma unroll
                for (int e = 0; e < 4; e++) s[j][e] = 0.f;

            #pragma unroll
            for (int ks = 0; ks < 4; ks++) {
                #pragma unroll
                for (int np = 0; np < 4; np++) {
                    uint32_t kh[4], kl[4];
                    const uint32_t ro = (np * 16 + (lane & 15)) * RSTRIDE +
                                        ((lane >> 4) << 4) + ks * 32;
                    ldsm4(kh, kb + ro);
                    ldsm4(kl, kb + KOFF_KL + ro);
                    mma_bf16(s[2 * np],     qh[ks], kh[0], kh[2]);
                    mma_bf16(s[2 * np],     qh[ks], kl[0], kl[2]);
                    mma_bf16(s[2 * np],     ql[ks], kh[0], kh[2]);
                    mma_bf16(s[2 * np + 1], qh[ks], kh[1], kh[3]);
                    mma_bf16(s[2 * np + 1], qh[ks], kl[1], kl[3]);
                    mma_bf16(s[2 * np + 1], ql[ks], kh[1], kh[3]);
                }
            }

            // ---- causal mask ----
            if (k0 + 63 > qmin) {
                #pragma unroll
                for (int j = 0; j < 8; j++) {
                    const int key = k0 + j * 8 + (lane & 3) * 2;
                    if (key     > r_lo)     s[j][0] = -1e30f;
                    if (key + 1 > r_lo)     s[j][1] = -1e30f;
                    if (key     > r_lo + 8) s[j][2] = -1e30f;
                    if (key + 1 > r_lo + 8) s[j][3] = -1e30f;
                }
            }

            // ---- online softmax (log2 domain) ----
            float rm0 = -1e30f, rm1 = -1e30f;
            #pragma unroll
            for (int j = 0; j < 8; j++) {
                rm0 = fmaxf(rm0, fmaxf(s[j][0], s[j][1]));
                rm1 = fmaxf(rm1, fmaxf(s[j][2], s[j][3]));
            }
            rm0 = fmaxf(rm0, __shfl_xor_sync(0xffffffff, rm0, 1));
            rm0 = fmaxf(rm0, __shfl_xor_sync(0xffffffff, rm0, 2));
            rm1 = fmaxf(rm1, __shfl_xor_sync(0xffffffff, rm1, 1));
            rm1 = fmaxf(rm1, __shfl_xor_sync(0xffffffff, rm1, 2));

            const float mn0 = fmaxf(m0, rm0), mn1 = fmaxf(m1, rm1);
            const float c0 = fexp2(m0 - mn0), c1 = fexp2(m1 - mn1);
            m0 = mn0; m1 = mn1;
            l0 *= c0; l1 *= c1;
            #pragma unroll
            for (int j = 0; j < 8; j++) {
                acc_o[j][0] *= c0; acc_o[j][1] *= c0;
                acc_o[j][2] *= c1; acc_o[j][3] *= c1;
            }

            float p[8][4];
            #pragma unroll
            for (int j = 0; j < 8; j++) {
                p[j][0] = fexp2(s[j][0] - m0);
                p[j][1] = fexp2(s[j][1] - m0);
                p[j][2] = fexp2(s[j][2] - m1);
                p[j][3] = fexp2(s[j][3] - m1);
                l0 += p[j][0] + p[j][1];
                l1 += p[j][2] + p[j][3];
            }

            // ---- pack P (hi & lo) ----
            uint32_t pha[4][4], pla[4][4];
            #pragma unroll
            for (int ks = 0; ks < 4; ks++) {
                const int j0 = 2 * ks, j1 = 2 * ks + 1;
                split_pack(p[j0][0], p[j0][1], pha[ks][0], pla[ks][0]);
                split_pack(p[j0][2], p[j0][3], pha[ks][1], pla[ks][1]);
                split_pack(p[j1][0], p[j1][1], pha[ks][2], pla[ks][2]);
                split_pack(p[j1][2], p[j1][3], pha[ks][3], pla[ks][3]);
            }

            // ---- O += P·V ----
            #pragma unroll
            for (int ks = 0; ks < 4; ks++) {
                #pragma unroll
                for (int np = 0; np < 4; np++) {
                    uint32_t vh[4], vl[4];
                    const int g = lane >> 3;
                    const uint32_t vrow = ks * 16 + (g & 1) * 8 + (lane & 7);
                    const uint32_t ro = vrow * RSTRIDE + np * 32 + (g >> 1) * 16;
                    ldsm4t(vh, kb + KOFF_VH + ro);
                    ldsm4t(vl, kb + KOFF_VL + ro);
                    mma_bf16(acc_o[2 * np],     pha[ks], vh[0], vh[1]);
                    mma_bf16(acc_o[2 * np],     pha[ks], vl[0], vl[1]);
                    mma_bf16(acc_o[2 * np],     pla[ks], vh[0], vh[1]);
                    mma_bf16(acc_o[2 * np + 1], pha[ks], vh[2], vh[3]);
                    mma_bf16(acc_o[2 * np + 1], pha[ks], vl[2], vl[3]);
                    mma_bf16(acc_o[2 * np + 1], pla[ks], vh[2], vh[3]);
                }
            }
        }
        __syncthreads();
    }

    // ---- epilogue: normalize, split, write [B*L, 1024] ----
    l0 += __shfl_xor_sync(0xffffffff, l0, 1);
    l0 += __shfl_xor_sync(0xffffffff, l0, 2);
    l1 += __shfl_xor_sync(0xffffffff, l1, 1);
    l1 += __shfl_xor_sync(0xffffffff, l1, 2);
    const float inv0 = 1.0f / l0, inv1 = 1.0f / l1;

    const size_t row0 = (size_t)(b * LL + q0 + wid * 16 + (lane >> 2));
    const size_t row1 = row0 + 8;
    const int colbase = h * HD + (lane & 3) * 2;
    #pragma unroll
    for (int j = 0; j < 8; j++) {
        const int col = colbase + j * 8;
        uint32_t hi, lo;
        split_pack(acc_o[j][0] * inv0, acc_o[j][1] * inv0, hi, lo);
        *(uint32_t*)(Oh + row0 * DD + col) = hi;
        *(uint32_t*)(Ol + row0 * DD + col) = lo;
        split_pack(acc_o[j][2] * inv1, acc_o[j][3] * inv1, hi, lo);
        *(uint32_t*)(Oh + row1 * DD + col) = hi;
        *(uint32_t*)(Ol + row1 * DD + col) = lo;
    }
}

// -------------------------------------------------------------------------
extern "C" void kernel_launch(void* const* d_in, const int* in_sizes, int n_in,
                              void* d_out, int out_size)
{
    const float* x        = (const float*)d_in[0];
    const float* rope_cos = (const float*)d_in[1];
    const float* rope_sin = (const float*)d_in[2];
    const float* W_qkv    = (const float*)d_in[3];
    const float* W_out    = (const float*)d_in[4];
    const float* b_out    = (const float*)d_in[5];
    float* out = (float*)d_out;

    float* qkv;
    cudaGetSymbolAddress((void**)&qkv, g_qkv);

    __nv_bfloat16 *xh, *xl, *wqh, *wql, *woh, *wol, *ath, *atl;
    __nv_bfloat16 *Qh, *Ql, *Kh, *Kl, *Vh, *Vl;
    cudaGetSymbolAddress((void**)&xh,  g_xh);
    cudaGetSymbolAddress((void**)&xl,  g_xl);
    cudaGetSymbolAddress((void**)&wqh, g_wqkvT_h);
    cudaGetSymbolAddress((void**)&wql, g_wqkvT_l);
    cudaGetSymbolAddress((void**)&woh, g_woutT_h);
    cudaGetSymbolAddress((void**)&wol, g_woutT_l);
    cudaGetSymbolAddress((void**)&ath, g_atth);
    cudaGetSymbolAddress((void**)&atl, g_attl);
    cudaGetSymbolAddress((void**)&Qh,  g_Qh);
    cudaGetSymbolAddress((void**)&Ql,  g_Ql);
    cudaGetSymbolAddress((void**)&Kh,  g_Kh);
    cudaGetSymbolAddress((void**)&Kl,  g_Kl);
    cudaGetSymbolAddress((void**)&Vh,  g_Vh);
    cudaGetSymbolAddress((void**)&Vl,  g_Vl);

    cudaFuncSetAttribute(flash_attn, cudaFuncAttributeMaxDynamicSharedMemorySize, ATT_SMEM);
    cudaFuncSetAttribute(mma_gemm<false>, cudaFuncAttributeMaxDynamicSharedMemorySize, GEMM_SMEM);
    cudaFuncSetAttribute(mma_gemm<true>,  cudaFuncAttributeMaxDynamicSharedMemorySize, GEMM_SMEM);

    // 0) operand conversion
    conv_split<<<(MROWS * DD / 4 + 255) / 256, 256>>>(x, xh, xl, MROWS * DD / 4);
    conv_splitT<<<dim3(NQKV / 32, DD / 32), dim3(32, 8)>>>(W_qkv, wqh, wql, DD, NQKV);
    conv_splitT<<<dim3(DD / 32, DD / 32),   dim3(32, 8)>>>(W_out, woh, wol, DD, DD);

    // 1) QKV projection on tensor cores (split bf16, 3-term, pipelined)
    mma_gemm<false><<<dim3(NQKV / GBN, MROWS / GBM), 256, GEMM_SMEM>>>(
        xh, xl, wqh, wql, nullptr, qkv, MROWS, NQKV, DD);

    // 2) RoPE + reshape + split to bf16 [B,H,L,HD]
    {
        const int total = BB * LL * HH * 32;
        rope_split<<<total / 256, 256>>>(qkv, rope_cos, rope_sin,
                                         Qh, Ql, Kh, Kl, Vh, Vl);
    }

    // 3) flash attention (tensor cores, pipelined KV) -> split bf16
    flash_attn<<<dim3(LL / 128, BB * HH), 256, ATT_SMEM>>>(
        Qh, Ql, Kh, Kl, Vh, Vl, ath, atl);

    // 4) output projection + bias
    mma_gemm<true><<<dim3(DD / GBN, MROWS / GBM), 256, GEMM_SMEM>>>(
        ath, atl, woh, wol, b_out, out, MROWS, DD, DD);
}

// round 6
// speedup vs baseline: 1.1222x; 1.1222x over previous
#include <cuda_runtime.h>
#include <cuda_bf16.h>
#include <cstdint>

// Problem constants
#define BB 2
#define LL 2048
#define DD 1024
#define HH 16
#define HD 64
#define NQKV 3072        // 3*H*HD
#define MROWS (BB*LL)    // 4096

// ---------------- scratch (device globals; no allocations allowed) -------
__device__ float g_qkv[MROWS * NQKV];             // [B*L, 3072] fp32

// split-bf16 operand buffers
__device__ __nv_bfloat16 g_xh[MROWS * DD];
__device__ __nv_bfloat16 g_xl[MROWS * DD];
__device__ __nv_bfloat16 g_wqkvT_h[NQKV * DD];    // [N][K]
__device__ __nv_bfloat16 g_wqkvT_l[NQKV * DD];
__device__ __nv_bfloat16 g_woutT_h[DD * DD];      // [N][K]
__device__ __nv_bfloat16 g_woutT_l[DD * DD];

// attention operands/results, split bf16, [B,H,L,HD] (Q scaled by 0.125*log2e)
__device__ __nv_bfloat16 g_Qh[BB * HH * LL * HD];
__device__ __nv_bfloat16 g_Ql[BB * HH * LL * HD];
__device__ __nv_bfloat16 g_Kh[BB * HH * LL * HD];
__device__ __nv_bfloat16 g_Kl[BB * HH * LL * HD];
__device__ __nv_bfloat16 g_Vh[BB * HH * LL * HD];
__device__ __nv_bfloat16 g_Vl[BB * HH * LL * HD];
__device__ __nv_bfloat16 g_atth[MROWS * DD];      // [B*L, 1024]
__device__ __nv_bfloat16 g_attl[MROWS * DD];

// ==================== helpers =============================================
__device__ __forceinline__ uint32_t smem_u32(const void* p) {
    uint32_t a;
    asm("{ .reg .u64 t; cvta.to.shared.u64 t, %1; cvt.u32.u64 %0, t; }"
        : "=r"(a) : "l"(p));
    return a;
}

__device__ __forceinline__ void split1(float v, __nv_bfloat16& hi, __nv_bfloat16& lo) {
    hi = __float2bfloat16(v);
    lo = __float2bfloat16(v - __bfloat162float(hi));
}

__device__ __forceinline__ uint32_t packbf(float lo, float hi) {
    uint32_t r;
    asm("cvt.rn.bf16x2.f32 %0, %1, %2;" : "=r"(r) : "f"(hi), "f"(lo));
    return r;
}

__device__ __forceinline__ void split_pack(float a, float b, uint32_t& hi, uint32_t& lo) {
    __nv_bfloat16 ah = __float2bfloat16(a), bh = __float2bfloat16(b);
    hi = (uint32_t)__bfloat16_as_ushort(ah) | ((uint32_t)__bfloat16_as_ushort(bh) << 16);
    lo = packbf(a - __bfloat162float(ah), b - __bfloat162float(bh));
}

__device__ __forceinline__ void ldsm4(uint32_t* r, uint32_t addr) {
    asm volatile("ldmatrix.sync.aligned.m8n8.x4.shared.b16 {%0,%1,%2,%3}, [%4];"
                 : "=r"(r[0]), "=r"(r[1]), "=r"(r[2]), "=r"(r[3]) : "r"(addr));
}

__device__ __forceinline__ void ldsm4t(uint32_t* r, uint32_t addr) {
    asm volatile("ldmatrix.sync.aligned.m8n8.x4.trans.shared.b16 {%0,%1,%2,%3}, [%4];"
                 : "=r"(r[0]), "=r"(r[1]), "=r"(r[2]), "=r"(r[3]) : "r"(addr));
}

__device__ __forceinline__ void mma_bf16(float* d, const uint32_t* a, uint32_t b0, uint32_t b1) {
    asm volatile(
        "mma.sync.aligned.m16n8k16.row.col.f32.bf16.bf16.f32 "
        "{%0,%1,%2,%3}, {%4,%5,%6,%7}, {%8,%9}, {%0,%1,%2,%3};"
        : "+f"(d[0]), "+f"(d[1]), "+f"(d[2]), "+f"(d[3])
        : "r"(a[0]), "r"(a[1]), "r"(a[2]), "r"(a[3]), "r"(b0), "r"(b1));
}

// cp.async with L1 caching (.ca) — weights are L1-reusable across CTAs
__device__ __forceinline__ void cpa16(uint32_t dst, const void* src) {
    asm volatile("cp.async.ca.shared.global [%0], [%1], 16;" :: "r"(dst), "l"(src));
}
#define CP_COMMIT() asm volatile("cp.async.commit_group;" ::: "memory")
#define CP_WAIT0()  asm volatile("cp.async.wait_group 0;" ::: "memory")
#define CP_WAIT1()  asm volatile("cp.async.wait_group 1;" ::: "memory")

// fast exp2 on FMA pipe (x <= 0 expected; clamped at -120)
__device__ __forceinline__ float fexp2(float x) {
    x = fmaxf(x, -120.0f);
    float n = floorf(x);
    float f = x - n;
    float p = 1.5404226e-4f;
    p = fmaf(p, f, 1.3333558e-3f);
    p = fmaf(p, f, 9.6181291e-3f);
    p = fmaf(p, f, 5.5504109e-2f);
    p = fmaf(p, f, 2.4022651e-1f);
    p = fmaf(p, f, 6.9314718e-1f);
    p = fmaf(p, f, 1.0f);
    return __int_as_float(__float_as_int(p) + (((int)n) << 23));
}

// ==================== conversion kernels ==================================
__global__ void conv_split(const float* __restrict__ src,
                           __nv_bfloat16* __restrict__ hi,
                           __nv_bfloat16* __restrict__ lo, int n4)
{
    const int i = blockIdx.x * blockDim.x + threadIdx.x;
    if (i >= n4) return;
    float4 v = ((const float4*)src)[i];
    __nv_bfloat16 h[4], l[4];
    split1(v.x, h[0], l[0]);
    split1(v.y, h[1], l[1]);
    split1(v.z, h[2], l[2]);
    split1(v.w, h[3], l[3]);
    ((uint2*)hi)[i] = *(uint2*)h;
    ((uint2*)lo)[i] = *(uint2*)l;
}

__global__ void conv_splitT(const float* __restrict__ W,
                            __nv_bfloat16* __restrict__ hiT,
                            __nv_bfloat16* __restrict__ loT,
                            int Kdim, int Ndim)
{
    __shared__ float t[32][33];
    const int tx = threadIdx.x, ty = threadIdx.y;
    const int nb = blockIdx.x * 32;
    const int kb = blockIdx.y * 32;
    #pragma unroll
    for (int i = 0; i < 4; i++)
        t[ty + i * 8][tx] = W[(size_t)(kb + ty + i * 8) * Ndim + nb + tx];
    __syncthreads();
    #pragma unroll
    for (int i = 0; i < 4; i++) {
        const float v = t[tx][ty + i * 8];
        __nv_bfloat16 h, l;
        split1(v, h, l);
        const size_t o = (size_t)(nb + ty + i * 8) * Kdim + kb + tx;
        hiT[o] = h;
        loT[o] = l;
    }
}

// ==================== warp-mma split-bf16 GEMM (cp.async 2-stage) =========
#define GBM 128
#define GBN 128
#define GBK 32
#define SROW 20                       // padded row stride (u32) = 80B
#define GOP  (GBM * SROW * 4)         // one operand buffer: 10240 B
// regions (x2 buffers each): AH, AL, BH, BL
#define GAH 0
#define GAL (2 * GOP)
#define GBH (4 * GOP)
#define GBL (6 * GOP)
#define GEMM_SMEM (8 * GOP)           // 81920 B

template <bool BIAS>
__global__ __launch_bounds__(256, 2)
void mma_gemm(const __nv_bfloat16* __restrict__ Ahg, const __nv_bfloat16* __restrict__ Alg,
              const __nv_bfloat16* __restrict__ Bhg, const __nv_bfloat16* __restrict__ Blg,
              const float* __restrict__ bias, float* __restrict__ C,
              int M, int Ntot, int K)
{
    extern __shared__ char gsm[];
    const uint32_t sb = smem_u32(gsm);

    const int tid = threadIdx.x;
    const int wid = tid >> 5;
    const int lane = tid & 31;
    const int warpM = wid & 3;
    const int warpN = wid >> 2;
    const int mBase = blockIdx.y * GBM;
    const int nBase = blockIdx.x * GBN;

    const uint32_t lrow = lane & 15;
    const uint32_t lhi  = (lane >> 4) << 4;

    float acc[2][8][4];
    #pragma unroll
    for (int a = 0; a < 2; a++)
        #pragma unroll
        for (int b = 0; b < 8; b++)
            #pragma unroll
            for (int c2 = 0; c2 < 4; c2++) acc[a][b][c2] = 0.f;

    const int row = tid >> 1;
    const int seg = tid & 1;
    const uint32_t so = (row * SROW + seg * 8) * 4;   // byte offset in buffer
    const int nchunks = K / GBK;

    auto stage = [&](int c, int buf) {
        const int k0 = c * GBK;
        const size_t ga = (size_t)(mBase + row) * K + k0 + seg * 16;
        const size_t gb = (size_t)(nBase + row) * K + k0 + seg * 16;
        const uint32_t bo = buf * GOP;
        cpa16(sb + GAH + bo + so,      Ahg + ga);
        cpa16(sb + GAH + bo + so + 16, Ahg + ga + 8);
        cpa16(sb + GAL + bo + so,      Alg + ga);
        cpa16(sb + GAL + bo + so + 16, Alg + ga + 8);
        cpa16(sb + GBH + bo + so,      Bhg + gb);
        cpa16(sb + GBH + bo + so + 16, Bhg + gb + 8);
        cpa16(sb + GBL + bo + so,      Blg + gb);
        cpa16(sb + GBL + bo + so + 16, Blg + gb + 8);
    };

    stage(0, 0);
    CP_COMMIT();

    for (int c = 0; c < nchunks; c++) {
        if (c + 1 < nchunks) {
            stage(c + 1, (c + 1) & 1);
            CP_COMMIT();
            CP_WAIT1();
        } else {
            CP_WAIT0();
        }
        __syncthreads();

        const uint32_t bo = (c & 1) * GOP;
        const uint32_t bAh = sb + GAH + bo, bAl = sb + GAL + bo;
        const uint32_t bBh = sb + GBH + bo, bBl = sb + GBL + bo;

        #pragma unroll
        for (int ks = 0; ks < 2; ks++) {
            const uint32_t kboff = ks * 32 + lhi;

            // ---- bulk-load ALL fragments for this k-step (12 LDSMs, MLP) ----
            uint32_t ah[2][4], al[2][4];
            uint32_t bh[4][4], bl[4][4];
            #pragma unroll
            for (int mt = 0; mt < 2; mt++) {
                const uint32_t ro = (warpM * 32 + mt * 16 + lrow) * (SROW * 4) + kboff;
                ldsm4(ah[mt], bAh + ro);
                ldsm4(al[mt], bAl + ro);
            }
            #pragma unroll
            for (int reg = 0; reg < 4; reg++) {
                const uint32_t ro = (warpN * 64 + reg * 16 + lrow) * (SROW * 4) + kboff;
                ldsm4(bh[reg], bBh + ro);
                ldsm4(bl[reg], bBl + ro);
            }

            // ---- then issue all 48 MMAs ----
            #pragma unroll
            for (int reg = 0; reg < 4; reg++) {
                #pragma unroll
                for (int mt = 0; mt < 2; mt++) {
                    #pragma unroll
                    for (int t = 0; t < 2; t++) {
                        float* d = acc[mt][reg * 2 + t];
                        mma_bf16(d, ah[mt], bh[reg][t], bh[reg][t + 2]);
                        mma_bf16(d, ah[mt], bl[reg][t], bl[reg][t + 2]);
                        mma_bf16(d, al[mt], bh[reg][t], bh[reg][t + 2]);
                    }
                }
            }
        }
        __syncthreads();
    }

    const int qrow = lane >> 2;
    const int qcol = (lane & 3) * 2;
    #pragma unroll
    for (int mt = 0; mt < 2; mt++) {
        const int m0 = mBase + warpM * 32 + mt * 16 + qrow;
        #pragma unroll
        for (int n8 = 0; n8 < 8; n8++) {
            const int col = nBase + warpN * 64 + n8 * 8 + qcol;
            float2 v0, v1;
            v0.x = acc[mt][n8][0]; v0.y = acc[mt][n8][1];
            v1.x = acc[mt][n8][2]; v1.y = acc[mt][n8][3];
            if (BIAS) {
                const float b0 = bias[col], b1 = bias[col + 1];
                v0.x += b0; v0.y += b1;
                v1.x += b0; v1.y += b1;
            }
            *(float2*)&C[(size_t)m0 * Ntot + col] = v0;
            *(float2*)&C[(size_t)(m0 + 8) * Ntot + col] = v1;
        }
    }
}

// --------------- RoPE + reshape + split to bf16 ---------------------------
__global__ void rope_split(const float* __restrict__ qkv,
                           const float* __restrict__ cosT,
                           const float* __restrict__ sinT,
                           __nv_bfloat16* __restrict__ Qh, __nv_bfloat16* __restrict__ Ql,
                           __nv_bfloat16* __restrict__ Kh, __nv_bfloat16* __restrict__ Kl,
                           __nv_bfloat16* __restrict__ Vh, __nv_bfloat16* __restrict__ Vl)
{
    const int idx = blockIdx.x * blockDim.x + threadIdx.x;
    if (idx >= BB * LL * HH * 32) return;
    const int d = idx & 31;
    const int h = (idx >> 5) & (HH - 1);
    const int l = (idx >> 9) & (LL - 1);
    const int b = idx >> 20;

    const float* row = qkv + ((size_t)(b * LL + l)) * NQKV;
    const float c0 = cosT[l * HD + d],      c1 = cosT[l * HD + d + 32];
    const float s0 = sinT[l * HD + d],      s1 = sinT[l * HD + d + 32];

    const float q0 = row[h * HD + d],            q1 = row[h * HD + d + 32];
    const float k0 = row[DD + h * HD + d],       k1 = row[DD + h * HD + d + 32];
    const float v0 = row[2 * DD + h * HD + d],   v1 = row[2 * DD + h * HD + d + 32];

    const float scale = 0.125f * 1.4426950408889634f;  // HD^-0.5 * log2(e)
    const size_t o = ((size_t)(b * HH + h) * LL + l) * HD;

    __nv_bfloat16 hi, lo;
    split1((q0 * c0 - q1 * s0) * scale, hi, lo); Qh[o + d] = hi;      Ql[o + d] = lo;
    split1((q1 * c1 + q0 * s1) * scale, hi, lo); Qh[o + d + 32] = hi; Ql[o + d + 32] = lo;
    split1(k0 * c0 - k1 * s0, hi, lo);           Kh[o + d] = hi;      Kl[o + d] = lo;
    split1(k1 * c1 + k0 * s1, hi, lo);           Kh[o + d + 32] = hi; Kl[o + d + 32] = lo;
    split1(v0, hi, lo);                          Vh[o + d] = hi;      Vl[o + d] = lo;
    split1(v1, hi, lo);                          Vh[o + d + 32] = hi; Vl[o + d + 32] = lo;
}

// --------------- flash attention (mma.sync, split bf16, cp.async) ---------
#define RSTRIDE 144               // padded smem row (72 bf16)
#define ASQH 0
#define ASQL 18432
#define KVB  36864                // KV double-buffer base
#define KVSZ 36864                // one KV buffer (KH,KL,VH,VL @ 9216 each)
#define KOFF_KL 9216
#define KOFF_VH 18432
#define KOFF_VL 27648
#define ATT_SMEM (KVB + 2 * KVSZ) // 110592

__global__ __launch_bounds__(256, 1)
void flash_attn(const __nv_bfloat16* __restrict__ Qhg, const __nv_bfloat16* __restrict__ Qlg,
                const __nv_bfloat16* __restrict__ Khg, const __nv_bfloat16* __restrict__ Klg,
                const __nv_bfloat16* __restrict__ Vhg, const __nv_bfloat16* __restrict__ Vlg,
                __nv_bfloat16* __restrict__ Oh, __nv_bfloat16* __restrict__ Ol)
{
    extern __shared__ char smem[];
    const uint32_t sb = smem_u32(smem);
    const int tid = threadIdx.x, wid = tid >> 5, lane = tid & 31;
    const int qt = (LL / 128 - 1) - blockIdx.x;     // big tiles first
    const int bh = blockIdx.y;
    const int b = bh >> 4, h = bh & 15;
    const int q0 = qt * 128;
    const size_t base = (size_t)bh * LL * HD;

    const int ntiles = q0 / 64 + 2;

    auto stage_kv = [&](int t, int buf) {
        const int k0 = t * 64;
        const uint32_t bo = KVB + buf * KVSZ;
        #pragma unroll
        for (int j = 0; j < 2; j++) {
            const int item = j * 256 + tid;
            const int row = item >> 3, seg = item & 7;
            const size_t g = base + (size_t)(k0 + row) * HD + seg * 8;
            const uint32_t so = bo + row * RSTRIDE + seg * 16;
            cpa16(sb + so,            Khg + g);
            cpa16(sb + so + KOFF_KL,  Klg + g);
            cpa16(sb + so + KOFF_VH,  Vhg + g);
            cpa16(sb + so + KOFF_VL,  Vlg + g);
        }
    };

    // ---- stage Q tile (hi & lo) + first KV tile ----
    {
        const int row = tid >> 1, seg = tid & 1;
        const size_t g = base + (size_t)(q0 + row) * HD + seg * 32;
        const uint32_t dh = sb + ASQH + row * RSTRIDE + seg * 64;
        const uint32_t dl = sb + ASQL + row * RSTRIDE + seg * 64;
        #pragma unroll
        for (int i = 0; i < 4; i++) {
            cpa16(dh + i * 16, Qhg + g + i * 8);
            cpa16(dl + i * 16, Qlg + g + i * 8);
        }
    }
    stage_kv(0, 0);
    CP_COMMIT();
    CP_WAIT0();
    __syncthreads();

    // ---- Q fragments (persistent) ----
    uint32_t qh[4][4], ql[4][4];
    {
        const uint32_t ro = (wid * 16 + (lane & 15)) * RSTRIDE + ((lane >> 4) << 4);
        #pragma unroll
        for (int ks = 0; ks < 4; ks++) {
            ldsm4(qh[ks], sb + ASQH + ro + ks * 32);
            ldsm4(ql[ks], sb + ASQL + ro + ks * 32);
        }
    }
    __syncthreads();

    float acc_o[8][4];
    #pragma unroll
    for (int j = 0; j < 8; j++)
        #pragma unroll
        for (int e = 0; e < 4; e++) acc_o[j][e] = 0.f;
    float m0 = -1e30f, m1 = -1e30f, l0 = 0.f, l1 = 0.f;

    const int qmin = q0 + wid * 16;
    const int r_lo = qmin + (lane >> 2);

    for (int t = 0; t < ntiles; t++) {
        const int k0 = t * 64;
        if (t + 1 < ntiles) {
            stage_kv(t + 1, (t + 1) & 1);
            CP_COMMIT();
            CP_WAIT1();
        } else {
            CP_WAIT0();
        }
        __syncthreads();

        if (k0 <= qmin + 15) {                     // not fully masked for this warp
            const uint32_t kb = sb + KVB + (t & 1) * KVSZ;

            // ---- S = Q·Kᵀ ----
            float s[8][4];
            #pragma unroll
            for (int j = 0; j < 8; j++)
                #pragma unroll
                for (int e = 0; e < 4; e++) s[j][e] = 0.f;

            #pragma unroll
            for (int ks = 0; ks < 4; ks++) {
                #pragma unroll
                for (int np = 0; np < 4; np++) {
                    uint32_t kh[4], kl[4];
                    const uint32_t ro = (np * 16 + (lane & 15)) * RSTRIDE +
                                        ((lane >> 4) << 4) + ks * 32;
                    ldsm4(kh, kb + ro);
                    ldsm4(kl, kb + KOFF_KL + ro);
                    mma_bf16(s[2 * np],     qh[ks], kh[0], kh[2]);
                    mma_bf16(s[2 * np],     qh[ks], kl[0], kl[2]);
                    mma_bf16(s[2 * np],     ql[ks], kh[0], kh[2]);
                    mma_bf16(s[2 * np + 1], qh[ks], kh[1], kh[3]);
                    mma_bf16(s[2 * np + 1], qh[ks], kl[1], kl[3]);
                    mma_bf16(s[2 * np + 1], ql[ks], kh[1], kh[3]);
                }
            }

            // ---- causal mask ----
            if (k0 + 63 > qmin) {
                #pragma unroll
                for (int j = 0; j < 8; j++) {
                    const int key = k0 + j * 8 + (lane & 3) * 2;
                    if (key     > r_lo)     s[j][0] = -1e30f;
                    if (key + 1 > r_lo)     s[j][1] = -1e30f;
                    if (key     > r_lo + 8) s[j][2] = -1e30f;
                    if (key + 1 > r_lo + 8) s[j][3] = -1e30f;
                }
            }

            // ---- online softmax (log2 domain) ----
            float rm0 = -1e30f, rm1 = -1e30f;
            #pragma unroll
            for (int j = 0; j < 8; j++) {
                rm0 = fmaxf(rm0, fmaxf(s[j][0], s[j][1]));
                rm1 = fmaxf(rm1, fmaxf(s[j][2], s[j][3]));
            }
            rm0 = fmaxf(rm0, __shfl_xor_sync(0xffffffff, rm0, 1));
            rm0 = fmaxf(rm0, __shfl_xor_sync(0xffffffff, rm0, 2));
            rm1 = fmaxf(rm1, __shfl_xor_sync(0xffffffff, rm1, 1));
            rm1 = fmaxf(rm1, __shfl_xor_sync(0xffffffff, rm1, 2));

            const float mn0 = fmaxf(m0, rm0), mn1 = fmaxf(m1, rm1);
            const float c0 = fexp2(m0 - mn0), c1 = fexp2(m1 - mn1);
            m0 = mn0; m1 = mn1;
            l0 *= c0; l1 *= c1;
            #pragma unroll
            for (int j = 0; j < 8; j++) {
                acc_o[j][0] *= c0; acc_o[j][1] *= c0;
                acc_o[j][2] *= c1; acc_o[j][3] *= c1;
            }

            float p[8][4];
            #pragma unroll
            for (int j = 0; j < 8; j++) {
                p[j][0] = fexp2(s[j][0] - m0);
                p[j][1] = fexp2(s[j][1] - m0);
                p[j][2] = fexp2(s[j][2] - m1);
                p[j][3] = fexp2(s[j][3] - m1);
                l0 += p[j][0] + p[j][1];
                l1 += p[j][2] + p[j][3];
            }

            // ---- pack P (hi & lo) ----
            uint32_t pha[4][4], pla[4][4];
            #pragma unroll
            for (int ks = 0; ks < 4; ks++) {
                const int j0 = 2 * ks, j1 = 2 * ks + 1;
                split_pack(p[j0][0], p[j0][1], pha[ks][0], pla[ks][0]);
                split_pack(p[j0][2], p[j0][3], pha[ks][1], pla[ks][1]);
                split_pack(p[j1][0], p[j1][1], pha[ks][2], pla[ks][2]);
                split_pack(p[j1][2], p[j1][3], pha[ks][3], pla[ks][3]);
            }

            // ---- O += P·V ----
            #pragma unroll
            for (int ks = 0; ks < 4; ks++) {
                #pragma unroll
                for (int np = 0; np < 4; np++) {
                    uint32_t vh[4], vl[4];
                    const int g = lane >> 3;
                    const uint32_t vrow = ks * 16 + (g & 1) * 8 + (lane & 7);
                    const uint32_t ro = vrow * RSTRIDE + np * 32 + (g >> 1) * 16;
                    ldsm4t(vh, kb + KOFF_VH + ro);
                    ldsm4t(vl, kb + KOFF_VL + ro);
                    mma_bf16(acc_o[2 * np],     pha[ks], vh[0], vh[1]);
                    mma_bf16(acc_o[2 * np],     pha[ks], vl[0], vl[1]);
                    mma_bf16(acc_o[2 * np],     pla[ks], vh[0], vh[1]);
                    mma_bf16(acc_o[2 * np + 1], pha[ks], vh[2], vh[3]);
                    mma_bf16(acc_o[2 * np + 1], pha[ks], vl[2], vl[3]);
                    mma_bf16(acc_o[2 * np + 1], pla[ks], vh[2], vh[3]);
                }
            }
        }
        __syncthreads();
    }

    // ---- epilogue: normalize, split, write [B*L, 1024] ----
    l0 += __shfl_xor_sync(0xffffffff, l0, 1);
    l0 += __shfl_xor_sync(0xffffffff, l0, 2);
    l1 += __shfl_xor_sync(0xffffffff, l1, 1);
    l1 += __shfl_xor_sync(0xffffffff, l1, 2);
    const float inv0 = 1.0f / l0, inv1 = 1.0f / l1;

    const size_t row0 = (size_t)(b * LL + q0 + wid * 16 + (lane >> 2));
    const size_t row1 = row0 + 8;
    const int colbase = h * HD + (lane & 3) * 2;
    #pragma unroll
    for (int j = 0; j < 8; j++) {
        const int col = colbase + j * 8;
        uint32_t hi, lo;
        split_pack(acc_o[j][0] * inv0, acc_o[j][1] * inv0, hi, lo);
        *(uint32_t*)(Oh + row0 * DD + col) = hi;
        *(uint32_t*)(Ol + row0 * DD + col) = lo;
        split_pack(acc_o[j][2] * inv1, acc_o[j][3] * inv1, hi, lo);
        *(uint32_t*)(Oh + row1 * DD + col) = hi;
        *(uint32_t*)(Ol + row1 * DD + col) = lo;
    }
}

// -------------------------------------------------------------------------
extern "C" void kernel_launch(void* const* d_in, const int* in_sizes, int n_in,
                              void* d_out, int out_size)
{
    const float* x        = (const float*)d_in[0];
    const float* rope_cos = (const float*)d_in[1];
    const float* rope_sin = (const float*)d_in[2];
    const float* W_qkv    = (const float*)d_in[3];
    const float* W_out    = (const float*)d_in[4];
    const float* b_out    = (const float*)d_in[5];
    float* out = (float*)d_out;

    float* qkv;
    cudaGetSymbolAddress((void**)&qkv, g_qkv);

    __nv_bfloat16 *xh, *xl, *wqh, *wql, *woh, *wol, *ath, *atl;
    __nv_bfloat16 *Qh, *Ql, *Kh, *Kl, *Vh, *Vl;
    cudaGetSymbolAddress((void**)&xh,  g_xh);
    cudaGetSymbolAddress((void**)&xl,  g_xl);
    cudaGetSymbolAddress((void**)&wqh, g_wqkvT_h);
    cudaGetSymbolAddress((void**)&wql, g_wqkvT_l);
    cudaGetSymbolAddress((void**)&woh, g_woutT_h);
    cudaGetSymbolAddress((void**)&wol, g_woutT_l);
    cudaGetSymbolAddress((void**)&ath, g_atth);
    cudaGetSymbolAddress((void**)&atl, g_attl);
    cudaGetSymbolAddress((void**)&Qh,  g_Qh);
    cudaGetSymbolAddress((void**)&Ql,  g_Ql);
    cudaGetSymbolAddress((void**)&Kh,  g_Kh);
    cudaGetSymbolAddress((void**)&Kl,  g_Kl);
    cudaGetSymbolAddress((void**)&Vh,  g_Vh);
    cudaGetSymbolAddress((void**)&Vl,  g_Vl);

    cudaFuncSetAttribute(flash_attn, cudaFuncAttributeMaxDynamicSharedMemorySize, ATT_SMEM);
    cudaFuncSetAttribute(mma_gemm<false>, cudaFuncAttributeMaxDynamicSharedMemorySize, GEMM_SMEM);
    cudaFuncSetAttribute(mma_gemm<true>,  cudaFuncAttributeMaxDynamicSharedMemorySize, GEMM_SMEM);

    // 0) operand conversion
    conv_split<<<(MROWS * DD / 4 + 255) / 256, 256>>>(x, xh, xl, MROWS * DD / 4);
    conv_splitT<<<dim3(NQKV / 32, DD / 32), dim3(32, 8)>>>(W_qkv, wqh, wql, DD, NQKV);
    conv_splitT<<<dim3(DD / 32, DD / 32),   dim3(32, 8)>>>(W_out, woh, wol, DD, DD);

    // 1) QKV projection on tensor cores (split bf16, 3-term, pipelined)
    mma_gemm<false><<<dim3(NQKV / GBN, MROWS / GBM), 256, GEMM_SMEM>>>(
        xh, xl, wqh, wql, nullptr, qkv, MROWS, NQKV, DD);

    // 2) RoPE + reshape + split to bf16 [B,H,L,HD]
    {
        const int total = BB * LL * HH * 32;
        rope_split<<<total / 256, 256>>>(qkv, rope_cos, rope_sin,
                                         Qh, Ql, Kh, Kl, Vh, Vl);
    }

    // 3) flash attention (tensor cores, pipelined KV) -> split bf16
    flash_attn<<<dim3(LL / 128, BB * HH), 256, ATT_SMEM>>>(
        Qh, Ql, Kh, Kl, Vh, Vl, ath, atl);

    // 4) output projection + bias
    mma_gemm<true><<<dim3(DD / GBN, MROWS / GBM), 256, GEMM_SMEM>>>(
        ath, atl, woh, wol, b_out, out, MROWS, DD, DD);
}

// round 7
// speedup vs baseline: 1.5076x; 1.3434x over previous
#include <cuda_runtime.h>
#include <cuda_fp16.h>
#include <cstdint>

// Problem constants
#define BB 2
#define LL 2048
#define DD 1024
#define HH 16
#define HD 64
#define NQKV 3072        // 3*H*HD
#define MROWS (BB*LL)    // 4096

// ---------------- scratch (device globals; no allocations allowed) -------
__device__ float g_qkv[MROWS * NQKV];             // [B*L, 3072] fp32

// fp16 operand buffers (2-term split: single-side A, paired-side B)
__device__ __half g_xf[MROWS * DD];               // x, single fp16
__device__ __half g_wqkvT_h[NQKV * DD];           // [N][K] hi
__device__ __half g_wqkvT_l[NQKV * DD];           // [N][K] lo
__device__ __half g_woutT_h[DD * DD];
__device__ __half g_woutT_l[DD * DD];

// attention operands/results, fp16, [B,H,L,HD] (Q scaled by 0.125*log2e)
__device__ __half g_Qf[BB * HH * LL * HD];        // single
__device__ __half g_Kh[BB * HH * LL * HD];
__device__ __half g_Kl[BB * HH * LL * HD];
__device__ __half g_Vh[BB * HH * LL * HD];
__device__ __half g_Vl[BB * HH * LL * HD];
__device__ __half g_attf[MROWS * DD];             // [B*L, 1024] single

// ==================== helpers =============================================
__device__ __forceinline__ uint32_t smem_u32(const void* p) {
    uint32_t a;
    asm("{ .reg .u64 t; cvta.to.shared.u64 t, %1; cvt.u32.u64 %0, t; }"
        : "=r"(a) : "l"(p));
    return a;
}

__device__ __forceinline__ void split1h(float v, __half& hi, __half& lo) {
    hi = __float2half_rn(v);
    lo = __float2half_rn(v - __half2float(hi));
}

// pack two floats -> half2 reg (a in low half)
__device__ __forceinline__ uint32_t pack2h(float a, float b) {
    __half2 h = __floats2half2_rn(a, b);
    return *(uint32_t*)&h;
}

__device__ __forceinline__ void ldsm4(uint32_t* r, uint32_t addr) {
    asm volatile("ldmatrix.sync.aligned.m8n8.x4.shared.b16 {%0,%1,%2,%3}, [%4];"
                 : "=r"(r[0]), "=r"(r[1]), "=r"(r[2]), "=r"(r[3]) : "r"(addr));
}

__device__ __forceinline__ void ldsm4t(uint32_t* r, uint32_t addr) {
    asm volatile("ldmatrix.sync.aligned.m8n8.x4.trans.shared.b16 {%0,%1,%2,%3}, [%4];"
                 : "=r"(r[0]), "=r"(r[1]), "=r"(r[2]), "=r"(r[3]) : "r"(addr));
}

__device__ __forceinline__ void mma_f16(float* d, const uint32_t* a, uint32_t b0, uint32_t b1) {
    asm volatile(
        "mma.sync.aligned.m16n8k16.row.col.f32.f16.f16.f32 "
        "{%0,%1,%2,%3}, {%4,%5,%6,%7}, {%8,%9}, {%0,%1,%2,%3};"
        : "+f"(d[0]), "+f"(d[1]), "+f"(d[2]), "+f"(d[3])
        : "r"(a[0]), "r"(a[1]), "r"(a[2]), "r"(a[3]), "r"(b0), "r"(b1));
}

// cp.async with L1 caching (.ca)
__device__ __forceinline__ void cpa16(uint32_t dst, const void* src) {
    asm volatile("cp.async.ca.shared.global [%0], [%1], 16;" :: "r"(dst), "l"(src));
}
#define CP_COMMIT() asm volatile("cp.async.commit_group;" ::: "memory")
#define CP_WAIT0()  asm volatile("cp.async.wait_group 0;" ::: "memory")
#define CP_WAIT1()  asm volatile("cp.async.wait_group 1;" ::: "memory")

// fast exp2 on FMA pipe (x <= 0 expected; clamped at -120)
__device__ __forceinline__ float fexp2(float x) {
    x = fmaxf(x, -120.0f);
    float n = floorf(x);
    float f = x - n;
    float p = 1.5404226e-4f;
    p = fmaf(p, f, 1.3333558e-3f);
    p = fmaf(p, f, 9.6181291e-3f);
    p = fmaf(p, f, 5.5504109e-2f);
    p = fmaf(p, f, 2.4022651e-1f);
    p = fmaf(p, f, 6.9314718e-1f);
    p = fmaf(p, f, 1.0f);
    return __int_as_float(__float_as_int(p) + (((int)n) << 23));
}

// ==================== conversion kernels ==================================
// fp32 -> single fp16
__global__ void conv_half(const float* __restrict__ src,
                          __half* __restrict__ dst, int n4)
{
    const int i = blockIdx.x * blockDim.x + threadIdx.x;
    if (i >= n4) return;
    float4 v = ((const float4*)src)[i];
    __half h[4];
    h[0] = __float2half_rn(v.x);
    h[1] = __float2half_rn(v.y);
    h[2] = __float2half_rn(v.z);
    h[3] = __float2half_rn(v.w);
    ((uint2*)dst)[i] = *(uint2*)h;
}

// W[K][N] fp32 -> hiT/loT [N][K] fp16 (transpose + split)
__global__ void conv_splitT(const float* __restrict__ W,
                            __half* __restrict__ hiT,
                            __half* __restrict__ loT,
                            int Kdim, int Ndim)
{
    __shared__ float t[32][33];
    const int tx = threadIdx.x, ty = threadIdx.y;
    const int nb = blockIdx.x * 32;
    const int kb = blockIdx.y * 32;
    #pragma unroll
    for (int i = 0; i < 4; i++)
        t[ty + i * 8][tx] = W[(size_t)(kb + ty + i * 8) * Ndim + nb + tx];
    __syncthreads();
    #pragma unroll
    for (int i = 0; i < 4; i++) {
        const float v = t[tx][ty + i * 8];
        __half h, l;
        split1h(v, h, l);
        const size_t o = (size_t)(nb + ty + i * 8) * Kdim + kb + tx;
        hiT[o] = h;
        loT[o] = l;
    }
}

// ==================== warp-mma fp16 2-term GEMM (cp.async 2-stage) ========
// C = A(single fp16) @ (Bh + Bl)^T, fp32 accum (+bias)
#define GBM 128
#define GBN 128
#define GBK 32
#define SROW 20                       // padded row stride (u32) = 80B
#define GOP  (GBM * SROW * 4)         // one operand buffer: 10240 B
#define GA   0                        // A  (2 buffers)
#define GBH  (2 * GOP)                // Bh (2 buffers)
#define GBL  (4 * GOP)                // Bl (2 buffers)
#define GEMM_SMEM (6 * GOP)           // 61440 B

template <bool BIAS>
__global__ __launch_bounds__(256, 2)
void mma_gemm(const __half* __restrict__ Afg,
              const __half* __restrict__ Bhg, const __half* __restrict__ Blg,
              const float* __restrict__ bias, float* __restrict__ C,
              int M, int Ntot, int K)
{
    extern __shared__ char gsm[];
    const uint32_t sb = smem_u32(gsm);

    const int tid = threadIdx.x;
    const int wid = tid >> 5;
    const int lane = tid & 31;
    const int warpM = wid & 3;
    const int warpN = wid >> 2;
    const int mBase = blockIdx.y * GBM;
    const int nBase = blockIdx.x * GBN;

    const uint32_t lrow = lane & 15;
    const uint32_t lhi  = (lane >> 4) << 4;

    float acc[2][8][4];
    #pragma unroll
    for (int a = 0; a < 2; a++)
        #pragma unroll
        for (int b = 0; b < 8; b++)
            #pragma unroll
            for (int c2 = 0; c2 < 4; c2++) acc[a][b][c2] = 0.f;

    const int row = tid >> 1;
    const int seg = tid & 1;
    const uint32_t so = (row * SROW + seg * 8) * 4;   // byte offset in buffer
    const int nchunks = K / GBK;

    auto stage = [&](int c, int buf) {
        const int k0 = c * GBK;
        const size_t ga = (size_t)(mBase + row) * K + k0 + seg * 16;
        const size_t gb = (size_t)(nBase + row) * K + k0 + seg * 16;
        const uint32_t bo = buf * GOP;
        cpa16(sb + GA  + bo + so,      Afg + ga);
        cpa16(sb + GA  + bo + so + 16, Afg + ga + 8);
        cpa16(sb + GBH + bo + so,      Bhg + gb);
        cpa16(sb + GBH + bo + so + 16, Bhg + gb + 8);
        cpa16(sb + GBL + bo + so,      Blg + gb);
        cpa16(sb + GBL + bo + so + 16, Blg + gb + 8);
    };

    stage(0, 0);
    CP_COMMIT();

    for (int c = 0; c < nchunks; c++) {
        if (c + 1 < nchunks) {
            stage(c + 1, (c + 1) & 1);
            CP_COMMIT();
            CP_WAIT1();
        } else {
            CP_WAIT0();
        }
        __syncthreads();

        const uint32_t bo = (c & 1) * GOP;
        const uint32_t bA = sb + GA + bo;
        const uint32_t bBh = sb + GBH + bo, bBl = sb + GBL + bo;

        #pragma unroll
        for (int ks = 0; ks < 2; ks++) {
            const uint32_t kboff = ks * 32 + lhi;

            // ---- bulk-load all fragments (10 LDSMs, MLP) ----
            uint32_t ah[2][4];
            uint32_t bh[4][4], bl[4][4];
            #pragma unroll
            for (int mt = 0; mt < 2; mt++) {
                const uint32_t ro = (warpM * 32 + mt * 16 + lrow) * (SROW * 4) + kboff;
                ldsm4(ah[mt], bA + ro);
            }
            #pragma unroll
            for (int reg = 0; reg < 4; reg++) {
                const uint32_t ro = (warpN * 64 + reg * 16 + lrow) * (SROW * 4) + kboff;
                ldsm4(bh[reg], bBh + ro);
                ldsm4(bl[reg], bBl + ro);
            }

            // ---- 32 MMAs (2 terms) ----
            #pragma unroll
            for (int reg = 0; reg < 4; reg++) {
                #pragma unroll
                for (int mt = 0; mt < 2; mt++) {
                    #pragma unroll
                    for (int t = 0; t < 2; t++) {
                        float* d = acc[mt][reg * 2 + t];
                        mma_f16(d, ah[mt], bh[reg][t], bh[reg][t + 2]);
                        mma_f16(d, ah[mt], bl[reg][t], bl[reg][t + 2]);
                    }
                }
            }
        }
        __syncthreads();
    }

    const int qrow = lane >> 2;
    const int qcol = (lane & 3) * 2;
    #pragma unroll
    for (int mt = 0; mt < 2; mt++) {
        const int m0 = mBase + warpM * 32 + mt * 16 + qrow;
        #pragma unroll
        for (int n8 = 0; n8 < 8; n8++) {
            const int col = nBase + warpN * 64 + n8 * 8 + qcol;
            float2 v0, v1;
            v0.x = acc[mt][n8][0]; v0.y = acc[mt][n8][1];
            v1.x = acc[mt][n8][2]; v1.y = acc[mt][n8][3];
            if (BIAS) {
                const float b0 = bias[col], b1 = bias[col + 1];
                v0.x += b0; v0.y += b1;
                v1.x += b0; v1.y += b1;
            }
            *(float2*)&C[(size_t)m0 * Ntot + col] = v0;
            *(float2*)&C[(size_t)(m0 + 8) * Ntot + col] = v1;
        }
    }
}

// --------------- RoPE + reshape + fp16 conversion -------------------------
// Q -> single fp16 (scaled by 0.125*log2e); K,V -> fp16 hi/lo pairs.
__global__ void rope_split(const float* __restrict__ qkv,
                           const float* __restrict__ cosT,
                           const float* __restrict__ sinT,
                           __half* __restrict__ Qf,
                           __half* __restrict__ Kh, __half* __restrict__ Kl,
                           __half* __restrict__ Vh, __half* __restrict__ Vl)
{
    const int idx = blockIdx.x * blockDim.x + threadIdx.x;
    if (idx >= BB * LL * HH * 32) return;
    const int d = idx & 31;
    const int h = (idx >> 5) & (HH - 1);
    const int l = (idx >> 9) & (LL - 1);
    const int b = idx >> 20;

    const float* row = qkv + ((size_t)(b * LL + l)) * NQKV;
    const float c0 = cosT[l * HD + d],      c1 = cosT[l * HD + d + 32];
    const float s0 = sinT[l * HD + d],      s1 = sinT[l * HD + d + 32];

    const float q0 = row[h * HD + d],            q1 = row[h * HD + d + 32];
    const float k0 = row[DD + h * HD + d],       k1 = row[DD + h * HD + d + 32];
    const float v0 = row[2 * DD + h * HD + d],   v1 = row[2 * DD + h * HD + d + 32];

    const float scale = 0.125f * 1.4426950408889634f;  // HD^-0.5 * log2(e)
    const size_t o = ((size_t)(b * HH + h) * LL + l) * HD;

    Qf[o + d]      = __float2half_rn((q0 * c0 - q1 * s0) * scale);
    Qf[o + d + 32] = __float2half_rn((q1 * c1 + q0 * s1) * scale);
    __half hi, lo;
    split1h(k0 * c0 - k1 * s0, hi, lo);  Kh[o + d] = hi;      Kl[o + d] = lo;
    split1h(k1 * c1 + k0 * s1, hi, lo);  Kh[o + d + 32] = hi; Kl[o + d + 32] = lo;
    split1h(v0, hi, lo);                 Vh[o + d] = hi;      Vl[o + d] = lo;
    split1h(v1, hi, lo);                 Vh[o + d + 32] = hi; Vl[o + d + 32] = lo;
}

// --------------- flash attention (mma.sync fp16, cp.async) ----------------
// Q single fp16; K,V hi/lo pairs. S = Q(Kh+Kl)ᵀ; O += P(Vh+Vl).
#define RSTRIDE 144               // padded smem row (72 fp16)
#define ASQ  0                    // Q region: 128 * 144 = 18432
#define KVB  18432                // KV double-buffer base
#define KVSZ 36864                // one KV buffer (KH,KL,VH,VL @ 9216 each)
#define KOFF_KL 9216
#define KOFF_VH 18432
#define KOFF_VL 27648
#define ATT_SMEM (KVB + 2 * KVSZ) // 92160

__global__ __launch_bounds__(256, 1)
void flash_attn(const __half* __restrict__ Qfg,
                const __half* __restrict__ Khg, const __half* __restrict__ Klg,
                const __half* __restrict__ Vhg, const __half* __restrict__ Vlg,
                __half* __restrict__ Of)
{
    extern __shared__ char smem[];
    const uint32_t sb = smem_u32(smem);
    const int tid = threadIdx.x, wid = tid >> 5, lane = tid & 31;
    const int qt = (LL / 128 - 1) - blockIdx.x;     // big tiles first
    const int bh = blockIdx.y;
    const int b = bh >> 4, h = bh & 15;
    const int q0 = qt * 128;
    const size_t base = (size_t)bh * LL * HD;

    const int ntiles = q0 / 64 + 2;

    auto stage_kv = [&](int t, int buf) {
        const int k0 = t * 64;
        const uint32_t bo = KVB + buf * KVSZ;
        #pragma unroll
        for (int j = 0; j < 2; j++) {
            const int item = j * 256 + tid;
            const int row = item >> 3, seg = item & 7;
            const size_t g = base + (size_t)(k0 + row) * HD + seg * 8;
            const uint32_t so = bo + row * RSTRIDE + seg * 16;
            cpa16(sb + so,            Khg + g);
            cpa16(sb + so + KOFF_KL,  Klg + g);
            cpa16(sb + so + KOFF_VH,  Vhg + g);
            cpa16(sb + so + KOFF_VL,  Vlg + g);
        }
    };

    // ---- stage Q tile + first KV tile ----
    {
        const int row = tid >> 1, seg = tid & 1;
        const size_t g = base + (size_t)(q0 + row) * HD + seg * 32;
        const uint32_t dq = sb + ASQ + row * RSTRIDE + seg * 64;
        #pragma unroll
        for (int i = 0; i < 4; i++)
            cpa16(dq + i * 16, Qfg + g + i * 8);
    }
    stage_kv(0, 0);
    CP_COMMIT();
    CP_WAIT0();
    __syncthreads();

    // ---- Q fragments (persistent) ----
    uint32_t qf[4][4];
    {
        const uint32_t ro = (wid * 16 + (lane & 15)) * RSTRIDE + ((lane >> 4) << 4);
        #pragma unroll
        for (int ks = 0; ks < 4; ks++)
            ldsm4(qf[ks], sb + ASQ + ro + ks * 32);
    }
    __syncthreads();

    float acc_o[8][4];
    #pragma unroll
    for (int j = 0; j < 8; j++)
        #pragma unroll
        for (int e = 0; e < 4; e++) acc_o[j][e] = 0.f;
    float m0 = -1e30f, m1 = -1e30f, l0 = 0.f, l1 = 0.f;

    const int qmin = q0 + wid * 16;
    const int r_lo = qmin + (lane >> 2);

    for (int t = 0; t < ntiles; t++) {
        const int k0 = t * 64;
        if (t + 1 < ntiles) {
            stage_kv(t + 1, (t + 1) & 1);
            CP_COMMIT();
            CP_WAIT1();
        } else {
            CP_WAIT0();
        }
        __syncthreads();

        if (k0 <= qmin + 15) {                     // not fully masked for this warp
            const uint32_t kb = sb + KVB + (t & 1) * KVSZ;

            // ---- S = Q·(Kh+Kl)ᵀ ----
            float s[8][4];
            #pragma unroll
            for (int j = 0; j < 8; j++)
                #pragma unroll
                for (int e = 0; e < 4; e++) s[j][e] = 0.f;

            #pragma unroll
            for (int ks = 0; ks < 4; ks++) {
                #pragma unroll
                for (int np = 0; np < 4; np++) {
                    uint32_t kh[4], kl[4];
                    const uint32_t ro = (np * 16 + (lane & 15)) * RSTRIDE +
                                        ((lane >> 4) << 4) + ks * 32;
                    ldsm4(kh, kb + ro);
                    ldsm4(kl, kb + KOFF_KL + ro);
                    mma_f16(s[2 * np],     qf[ks], kh[0], kh[2]);
                    mma_f16(s[2 * np],     qf[ks], kl[0], kl[2]);
                    mma_f16(s[2 * np + 1], qf[ks], kh[1], kh[3]);
                    mma_f16(s[2 * np + 1], qf[ks], kl[1], kl[3]);
                }
            }

            // ---- causal mask ----
            if (k0 + 63 > qmin) {
                #pragma unroll
                for (int j = 0; j < 8; j++) {
                    const int key = k0 + j * 8 + (lane & 3) * 2;
                    if (key     > r_lo)     s[j][0] = -1e30f;
                    if (key + 1 > r_lo)     s[j][1] = -1e30f;
                    if (key     > r_lo + 8) s[j][2] = -1e30f;
                    if (key + 1 > r_lo + 8) s[j][3] = -1e30f;
                }
            }

            // ---- online softmax (log2 domain) ----
            float rm0 = -1e30f, rm1 = -1e30f;
            #pragma unroll
            for (int j = 0; j < 8; j++) {
                rm0 = fmaxf(rm0, fmaxf(s[j][0], s[j][1]));
                rm1 = fmaxf(rm1, fmaxf(s[j][2], s[j][3]));
            }
            rm0 = fmaxf(rm0, __shfl_xor_sync(0xffffffff, rm0, 1));
            rm0 = fmaxf(rm0, __shfl_xor_sync(0xffffffff, rm0, 2));
            rm1 = fmaxf(rm1, __shfl_xor_sync(0xffffffff, rm1, 1));
            rm1 = fmaxf(rm1, __shfl_xor_sync(0xffffffff, rm1, 2));

            const float mn0 = fmaxf(m0, rm0), mn1 = fmaxf(m1, rm1);
            const float c0 = fexp2(m0 - mn0), c1 = fexp2(m1 - mn1);
            m0 = mn0; m1 = mn1;
            l0 *= c0; l1 *= c1;
            #pragma unroll
            for (int j = 0; j < 8; j++) {
                acc_o[j][0] *= c0; acc_o[j][1] *= c0;
                acc_o[j][2] *= c1; acc_o[j][3] *= c1;
            }

            float p[8][4];
            #pragma unroll
            for (int j = 0; j < 8; j++) {
                p[j][0] = fexp2(s[j][0] - m0);
                p[j][1] = fexp2(s[j][1] - m0);
                p[j][2] = fexp2(s[j][2] - m1);
                p[j][3] = fexp2(s[j][3] - m1);
                l0 += p[j][0] + p[j][1];
                l1 += p[j][2] + p[j][3];
            }

            // ---- pack P (single fp16) ----
            uint32_t pf[4][4];
            #pragma unroll
            for (int ks = 0; ks < 4; ks++) {
                const int j0 = 2 * ks, j1 = 2 * ks + 1;
                pf[ks][0] = pack2h(p[j0][0], p[j0][1]);
                pf[ks][1] = pack2h(p[j0][2], p[j0][3]);
                pf[ks][2] = pack2h(p[j1][0], p[j1][1]);
                pf[ks][3] = pack2h(p[j1][2], p[j1][3]);
            }

            // ---- O += P·(Vh+Vl) ----
            #pragma unroll
            for (int ks = 0; ks < 4; ks++) {
                #pragma unroll
                for (int np = 0; np < 4; np++) {
                    uint32_t vh[4], vl[4];
                    const int g = lane >> 3;
                    const uint32_t vrow = ks * 16 + (g & 1) * 8 + (lane & 7);
                    const uint32_t ro = vrow * RSTRIDE + np * 32 + (g >> 1) * 16;
                    ldsm4t(vh, kb + KOFF_VH + ro);
                    ldsm4t(vl, kb + KOFF_VL + ro);
                    mma_f16(acc_o[2 * np],     pf[ks], vh[0], vh[1]);
                    mma_f16(acc_o[2 * np],     pf[ks], vl[0], vl[1]);
                    mma_f16(acc_o[2 * np + 1], pf[ks], vh[2], vh[3]);
                    mma_f16(acc_o[2 * np + 1], pf[ks], vl[2], vl[3]);
                }
            }
        }
        __syncthreads();
    }

    // ---- epilogue: normalize, write single fp16 [B*L, 1024] ----
    l0 += __shfl_xor_sync(0xffffffff, l0, 1);
    l0 += __shfl_xor_sync(0xffffffff, l0, 2);
    l1 += __shfl_xor_sync(0xffffffff, l1, 1);
    l1 += __shfl_xor_sync(0xffffffff, l1, 2);
    const float inv0 = 1.0f / l0, inv1 = 1.0f / l1;

    const size_t row0 = (size_t)(b * LL + q0 + wid * 16 + (lane >> 2));
    const size_t row1 = row0 + 8;
    const int colbase = h * HD + (lane & 3) * 2;
    #pragma unroll
    for (int j = 0; j < 8; j++) {
        const int col = colbase + j * 8;
        *(uint32_t*)(Of + row0 * DD + col) = pack2h(acc_o[j][0] * inv0, acc_o[j][1] * inv0);
        *(uint32_t*)(Of + row1 * DD + col) = pack2h(acc_o[j][2] * inv1, acc_o[j][3] * inv1);
    }
}

// -------------------------------------------------------------------------
extern "C" void kernel_launch(void* const* d_in, const int* in_sizes, int n_in,
                              void* d_out, int out_size)
{
    const float* x        = (const float*)d_in[0];
    const float* rope_cos = (const float*)d_in[1];
    const float* rope_sin = (const float*)d_in[2];
    const float* W_qkv    = (const float*)d_in[3];
    const float* W_out    = (const float*)d_in[4];
    const float* b_out    = (const float*)d_in[5];
    float* out = (float*)d_out;

    float* qkv;
    cudaGetSymbolAddress((void**)&qkv, g_qkv);

    __half *xf, *wqh, *wql, *woh, *wol, *attf;
    __half *Qf, *Kh, *Kl, *Vh, *Vl;
    cudaGetSymbolAddress((void**)&xf,   g_xf);
    cudaGetSymbolAddress((void**)&wqh,  g_wqkvT_h);
    cudaGetSymbolAddress((void**)&wql,  g_wqkvT_l);
    cudaGetSymbolAddress((void**)&woh,  g_woutT_h);
    cudaGetSymbolAddress((void**)&wol,  g_woutT_l);
    cudaGetSymbolAddress((void**)&attf, g_attf);
    cudaGetSymbolAddress((void**)&Qf,   g_Qf);
    cudaGetSymbolAddress((void**)&Kh,   g_Kh);
    cudaGetSymbolAddress((void**)&Kl,   g_Kl);
    cudaGetSymbolAddress((void**)&Vh,   g_Vh);
    cudaGetSymbolAddress((void**)&Vl,   g_Vl);

    cudaFuncSetAttribute(flash_attn, cudaFuncAttributeMaxDynamicSharedMemorySize, ATT_SMEM);
    cudaFuncSetAttribute(mma_gemm<false>, cudaFuncAttributeMaxDynamicSharedMemorySize, GEMM_SMEM);
    cudaFuncSetAttribute(mma_gemm<true>,  cudaFuncAttributeMaxDynamicSharedMemorySize, GEMM_SMEM);

    // 0) operand conversion
    conv_half<<<(MROWS * DD / 4 + 255) / 256, 256>>>(x, xf, MROWS * DD / 4);
    conv_splitT<<<dim3(NQKV / 32, DD / 32), dim3(32, 8)>>>(W_qkv, wqh, wql, DD, NQKV);
    conv_splitT<<<dim3(DD / 32, DD / 32),   dim3(32, 8)>>>(W_out, woh, wol, DD, DD);

    // 1) QKV projection (fp16 2-term, pipelined)
    mma_gemm<false><<<dim3(NQKV / GBN, MROWS / GBM), 256, GEMM_SMEM>>>(
        xf, wqh, wql, nullptr, qkv, MROWS, NQKV, DD);

    // 2) RoPE + reshape + fp16 conversion [B,H,L,HD]
    {
        const int total = BB * LL * HH * 32;
        rope_split<<<total / 256, 256>>>(qkv, rope_cos, rope_sin,
                                         Qf, Kh, Kl, Vh, Vl);
    }

    // 3) flash attention (fp16 tensor cores, pipelined KV) -> fp16
    flash_attn<<<dim3(LL / 128, BB * HH), 256, ATT_SMEM>>>(
        Qf, Kh, Kl, Vh, Vl, attf);

    // 4) output projection + bias (fp16 2-term)
    mma_gemm<true><<<dim3(DD / GBN, MROWS / GBM), 256, GEMM_SMEM>>>(
        attf, woh, wol, b_out, out, MROWS, DD, DD);
}

// round 8
// speedup vs baseline: 1.5213x; 1.0091x over previous
#include <cuda_runtime.h>
#include <cuda_fp16.h>
#include <cstdint>

// Problem constants
#define BB 2
#define LL 2048
#define DD 1024
#define HH 16
#define HD 64
#define NQKV 3072        // 3*H*HD
#define MROWS (BB*LL)    // 4096

// ---------------- scratch (device globals; no allocations allowed) -------
// fp16 operand buffers (2-term split: single-side A, paired-side B)
__device__ __half g_xf[MROWS * DD];               // x, single fp16
__device__ __half g_wqkvT_h[NQKV * DD];           // [N][K] hi
__device__ __half g_wqkvT_l[NQKV * DD];           // [N][K] lo
__device__ __half g_woutT_h[DD * DD];
__device__ __half g_woutT_l[DD * DD];

// attention operands/results, fp16, [B,H,L,HD] (Q scaled by 0.125*log2e)
__device__ __half g_Qf[BB * HH * LL * HD];        // single
__device__ __half g_Kh[BB * HH * LL * HD];
__device__ __half g_Kl[BB * HH * LL * HD];
__device__ __half g_Vh[BB * HH * LL * HD];
__device__ __half g_Vl[BB * HH * LL * HD];
__device__ __half g_attf[MROWS * DD];             // [B*L, 1024] single

// ==================== helpers =============================================
__device__ __forceinline__ uint32_t smem_u32(const void* p) {
    uint32_t a;
    asm("{ .reg .u64 t; cvta.to.shared.u64 t, %1; cvt.u32.u64 %0, t; }"
        : "=r"(a) : "l"(p));
    return a;
}

__device__ __forceinline__ void split1h(float v, __half& hi, __half& lo) {
    hi = __float2half_rn(v);
    lo = __float2half_rn(v - __half2float(hi));
}

// pack two floats -> half2 reg (a in low half)
__device__ __forceinline__ uint32_t pack2h(float a, float b) {
    __half2 h = __floats2half2_rn(a, b);
    return *(uint32_t*)&h;
}

// split two floats into hi-pair / lo-pair fp16x2 regs
__device__ __forceinline__ void split_pack_h(float a, float b, uint32_t& hi, uint32_t& lo) {
    __half ah = __float2half_rn(a), bh = __float2half_rn(b);
    __half2 hh; hh.x = ah; hh.y = bh;
    hi = *(uint32_t*)&hh;
    lo = pack2h(a - __half2float(ah), b - __half2float(bh));
}

__device__ __forceinline__ void ldsm4(uint32_t* r, uint32_t addr) {
    asm volatile("ldmatrix.sync.aligned.m8n8.x4.shared.b16 {%0,%1,%2,%3}, [%4];"
                 : "=r"(r[0]), "=r"(r[1]), "=r"(r[2]), "=r"(r[3]) : "r"(addr));
}

__device__ __forceinline__ void ldsm4t(uint32_t* r, uint32_t addr) {
    asm volatile("ldmatrix.sync.aligned.m8n8.x4.trans.shared.b16 {%0,%1,%2,%3}, [%4];"
                 : "=r"(r[0]), "=r"(r[1]), "=r"(r[2]), "=r"(r[3]) : "r"(addr));
}

__device__ __forceinline__ void mma_f16(float* d, const uint32_t* a, uint32_t b0, uint32_t b1) {
    asm volatile(
        "mma.sync.aligned.m16n8k16.row.col.f32.f16.f16.f32 "
        "{%0,%1,%2,%3}, {%4,%5,%6,%7}, {%8,%9}, {%0,%1,%2,%3};"
        : "+f"(d[0]), "+f"(d[1]), "+f"(d[2]), "+f"(d[3])
        : "r"(a[0]), "r"(a[1]), "r"(a[2]), "r"(a[3]), "r"(b0), "r"(b1));
}

// cp.async with L1 caching (.ca)
__device__ __forceinline__ void cpa16(uint32_t dst, const void* src) {
    asm volatile("cp.async.ca.shared.global [%0], [%1], 16;" :: "r"(dst), "l"(src));
}
#define CP_COMMIT() asm volatile("cp.async.commit_group;" ::: "memory")
#define CP_WAIT0()  asm volatile("cp.async.wait_group 0;" ::: "memory")
#define CP_WAIT1()  asm volatile("cp.async.wait_group 1;" ::: "memory")

// fast exp2 on FMA pipe (x <= 0 expected; clamped at -120)
__device__ __forceinline__ float fexp2(float x) {
    x = fmaxf(x, -120.0f);
    float n = floorf(x);
    float f = x - n;
    float p = 1.5404226e-4f;
    p = fmaf(p, f, 1.3333558e-3f);
    p = fmaf(p, f, 9.6181291e-3f);
    p = fmaf(p, f, 5.5504109e-2f);
    p = fmaf(p, f, 2.4022651e-1f);
    p = fmaf(p, f, 6.9314718e-1f);
    p = fmaf(p, f, 1.0f);
    return __int_as_float(__float_as_int(p) + (((int)n) << 23));
}

// ==================== conversion kernels ==================================
__global__ void conv_half(const float* __restrict__ src,
                          __half* __restrict__ dst, int n4)
{
    const int i = blockIdx.x * blockDim.x + threadIdx.x;
    if (i >= n4) return;
    float4 v = ((const float4*)src)[i];
    __half h[4];
    h[0] = __float2half_rn(v.x);
    h[1] = __float2half_rn(v.y);
    h[2] = __float2half_rn(v.z);
    h[3] = __float2half_rn(v.w);
    ((uint2*)dst)[i] = *(uint2*)h;
}

__global__ void conv_splitT(const float* __restrict__ W,
                            __half* __restrict__ hiT,
                            __half* __restrict__ loT,
                            int Kdim, int Ndim)
{
    __shared__ float t[32][33];
    const int tx = threadIdx.x, ty = threadIdx.y;
    const int nb = blockIdx.x * 32;
    const int kb = blockIdx.y * 32;
    #pragma unroll
    for (int i = 0; i < 4; i++)
        t[ty + i * 8][tx] = W[(size_t)(kb + ty + i * 8) * Ndim + nb + tx];
    __syncthreads();
    #pragma unroll
    for (int i = 0; i < 4; i++) {
        const float v = t[tx][ty + i * 8];
        __half h, l;
        split1h(v, h, l);
        const size_t o = (size_t)(nb + ty + i * 8) * Kdim + kb + tx;
        hiT[o] = h;
        loT[o] = l;
    }
}

// ==================== GEMM common (fp16 2-term, 3-stage cp.async ring) ====
#define GBM 128
#define GBN 128
#define GBK 32
#define SROW 20                       // padded row stride (u32) = 80B
#define GOP  (GBM * SROW * 4)         // one operand buffer: 10240 B
#define GA   0                        // A  (3 buffers)
#define GBH  (3 * GOP)                // Bh (3 buffers)
#define GBL  (6 * GOP)                // Bl (3 buffers)
#define GEMM_SMEM (9 * GOP)           // 92160 B

// mainloop macro body shared by the two GEMM kernels via an inline function
struct GemmCtx {
    uint32_t sb;
    int warpM, warpN, lane;
    int mBase, nBase;
};

__device__ __forceinline__ void gemm_mainloop(
    const GemmCtx& g, const __half* Afg, const __half* Bhg, const __half* Blg,
    int K, int tid, float acc[2][8][4])
{
    const int row = tid >> 1;
    const int seg = tid & 1;
    const uint32_t so = (row * SROW + seg * 8) * 4;
    const int nchunks = K / GBK;
    const uint32_t lrow = g.lane & 15;
    const uint32_t lhi  = (g.lane >> 4) << 4;

    auto stage = [&](int c, int buf) {
        const int k0 = c * GBK;
        const size_t ga = (size_t)(g.mBase + row) * K + k0 + seg * 16;
        const size_t gb = (size_t)(g.nBase + row) * K + k0 + seg * 16;
        const uint32_t bo = buf * GOP;
        cpa16(g.sb + GA  + bo + so,      Afg + ga);
        cpa16(g.sb + GA  + bo + so + 16, Afg + ga + 8);
        cpa16(g.sb + GBH + bo + so,      Bhg + gb);
        cpa16(g.sb + GBH + bo + so + 16, Bhg + gb + 8);
        cpa16(g.sb + GBL + bo + so,      Blg + gb);
        cpa16(g.sb + GBL + bo + so + 16, Blg + gb + 8);
    };

    stage(0, 0); CP_COMMIT();
    stage(1, 1); CP_COMMIT();

    for (int c = 0; c < nchunks; c++) {
        if (c + 1 < nchunks) { CP_WAIT1(); } else { CP_WAIT0(); }
        __syncthreads();

        const uint32_t bo = (c % 3) * GOP;
        const uint32_t bA = g.sb + GA + bo;
        const uint32_t bBh = g.sb + GBH + bo, bBl = g.sb + GBL + bo;

        #pragma unroll
        for (int ks = 0; ks < 2; ks++) {
            const uint32_t kboff = ks * 32 + lhi;
            uint32_t ah[2][4];
            uint32_t bh[4][4], bl[4][4];
            #pragma unroll
            for (int mt = 0; mt < 2; mt++) {
                const uint32_t ro = (g.warpM * 32 + mt * 16 + lrow) * (SROW * 4) + kboff;
                ldsm4(ah[mt], bA + ro);
            }
            #pragma unroll
            for (int reg = 0; reg < 4; reg++) {
                const uint32_t ro = (g.warpN * 64 + reg * 16 + lrow) * (SROW * 4) + kboff;
                ldsm4(bh[reg], bBh + ro);
                ldsm4(bl[reg], bBl + ro);
            }
            #pragma unroll
            for (int reg = 0; reg < 4; reg++) {
                #pragma unroll
                for (int mt = 0; mt < 2; mt++) {
                    #pragma unroll
                    for (int t = 0; t < 2; t++) {
                        float* d = acc[mt][reg * 2 + t];
                        mma_f16(d, ah[mt], bh[reg][t], bh[reg][t + 2]);
                        mma_f16(d, ah[mt], bl[reg][t], bl[reg][t + 2]);
                    }
                }
            }
        }

        if (c + 2 < nchunks) { stage(c + 2, (c + 2) % 3); CP_COMMIT(); }
    }
}

// ---- QKV GEMM with fused RoPE + split epilogue ---------------------------
__global__ __launch_bounds__(256, 2)
void mma_gemm_qkv(const __half* __restrict__ Afg,
                  const __half* __restrict__ Bhg, const __half* __restrict__ Blg,
                  const float* __restrict__ cosT, const float* __restrict__ sinT,
                  __half* __restrict__ Qf,
                  __half* __restrict__ Kh, __half* __restrict__ Kl,
                  __half* __restrict__ Vh, __half* __restrict__ Vl)
{
    extern __shared__ char gsm[];
    const int tid = threadIdx.x;
    GemmCtx g;
    g.sb = smem_u32(gsm);
    g.lane = tid & 31;
    const int wid = tid >> 5;
    g.warpM = wid & 3;
    g.warpN = wid >> 2;
    g.mBase = blockIdx.y * GBM;
    g.nBase = blockIdx.x * GBN;

    float acc[2][8][4];
    #pragma unroll
    for (int a = 0; a < 2; a++)
        #pragma unroll
        for (int b = 0; b < 8; b++)
            #pragma unroll
            for (int c2 = 0; c2 < 4; c2++) acc[a][b][c2] = 0.f;

    gemm_mainloop(g, Afg, Bhg, Blg, DD, tid, acc);

    // ---- fused epilogue: RoPE (Q,K) + hi/lo split (K,V) + store ----
    const int qrow = g.lane >> 2;
    const int qcol = (g.lane & 3) * 2;
    const float qscale = 0.125f * 1.4426950408889634f;  // HD^-0.5 * log2(e)

    #pragma unroll
    for (int mt = 0; mt < 2; mt++) {
        const int r0 = g.mBase + g.warpM * 32 + mt * 16 + qrow;
        const int b  = r0 >> 11;          // /LL
        const int l0 = r0 & (LL - 1);
        const int l1 = l0 + 8;
        #pragma unroll
        for (int n8 = 0; n8 < 4; n8++) {
            const int col = g.nBase + g.warpN * 64 + n8 * 8 + qcol;
            const int d   = n8 * 8 + qcol;          // 0..31 within head
            const int h3  = col >> 6;
            const int sec = h3 >> 4;                // 0=Q 1=K 2=V
            const int h   = h3 & 15;
            const size_t o0 = (((size_t)(b * HH + h) * LL) + l0) * HD;
            const size_t o1 = o0 + 8 * HD;

            const float a0 = acc[mt][n8][0], a1 = acc[mt][n8][1];
            const float a2 = acc[mt][n8][2], a3 = acc[mt][n8][3];
            const float b0 = acc[mt][n8 + 4][0], b1 = acc[mt][n8 + 4][1];
            const float b2 = acc[mt][n8 + 4][2], b3 = acc[mt][n8 + 4][3];

            if (sec == 2) {
                uint32_t hi, lo;
                split_pack_h(a0, a1, hi, lo);
                *(uint32_t*)(Vh + o0 + d) = hi;      *(uint32_t*)(Vl + o0 + d) = lo;
                split_pack_h(a2, a3, hi, lo);
                *(uint32_t*)(Vh + o1 + d) = hi;      *(uint32_t*)(Vl + o1 + d) = lo;
                split_pack_h(b0, b1, hi, lo);
                *(uint32_t*)(Vh + o0 + d + 32) = hi; *(uint32_t*)(Vl + o0 + d + 32) = lo;
                split_pack_h(b2, b3, hi, lo);
                *(uint32_t*)(Vh + o1 + d + 32) = hi; *(uint32_t*)(Vl + o1 + d + 32) = lo;
            } else {
                // cos/sin for both rows, both halves (float2: d,d+1 contiguous)
                const float2 cl0 = *(const float2*)(cosT + l0 * HD + d);
                const float2 ch0 = *(const float2*)(cosT + l0 * HD + d + 32);
                const float2 sl0 = *(const float2*)(sinT + l0 * HD + d);
                const float2 sh0 = *(const float2*)(sinT + l0 * HD + d + 32);
                const float2 cl1 = *(const float2*)(cosT + l1 * HD + d);
                const float2 ch1 = *(const float2*)(cosT + l1 * HD + d + 32);
                const float2 sl1 = *(const float2*)(sinT + l1 * HD + d);
                const float2 sh1 = *(const float2*)(sinT + l1 * HD + d + 32);

                // row l0
                float rl0 = a0 * cl0.x - b0 * sl0.x;
                float rl1 = a1 * cl0.y - b1 * sl0.y;
                float rh0 = b0 * ch0.x + a0 * sh0.x;
                float rh1 = b1 * ch0.y + a1 * sh0.y;
                // row l1
                float ql0 = a2 * cl1.x - b2 * sl1.x;
                float ql1 = a3 * cl1.y - b3 * sl1.y;
                float qh0 = b2 * ch1.x + a2 * sh1.x;
                float qh1 = b3 * ch1.y + a3 * sh1.y;

                if (sec == 0) {
                    *(uint32_t*)(Qf + o0 + d)      = pack2h(rl0 * qscale, rl1 * qscale);
                    *(uint32_t*)(Qf + o0 + d + 32) = pack2h(rh0 * qscale, rh1 * qscale);
                    *(uint32_t*)(Qf + o1 + d)      = pack2h(ql0 * qscale, ql1 * qscale);
                    *(uint32_t*)(Qf + o1 + d + 32) = pack2h(qh0 * qscale, qh1 * qscale);
                } else {
                    uint32_t hi, lo;
                    split_pack_h(rl0, rl1, hi, lo);
                    *(uint32_t*)(Kh + o0 + d) = hi;      *(uint32_t*)(Kl + o0 + d) = lo;
                    split_pack_h(rh0, rh1, hi, lo);
                    *(uint32_t*)(Kh + o0 + d + 32) = hi; *(uint32_t*)(Kl + o0 + d + 32) = lo;
                    split_pack_h(ql0, ql1, hi, lo);
                    *(uint32_t*)(Kh + o1 + d) = hi;      *(uint32_t*)(Kl + o1 + d) = lo;
                    split_pack_h(qh0, qh1, hi, lo);
                    *(uint32_t*)(Kh + o1 + d + 32) = hi; *(uint32_t*)(Kl + o1 + d + 32) = lo;
                }
            }
        }
    }
}

// ---- output projection GEMM (+bias), fp32 out ----------------------------
__global__ __launch_bounds__(256, 2)
void mma_gemm_bias(const __half* __restrict__ Afg,
                   const __half* __restrict__ Bhg, const __half* __restrict__ Blg,
                   const float* __restrict__ bias, float* __restrict__ C,
                   int Ntot, int K)
{
    extern __shared__ char gsm[];
    const int tid = threadIdx.x;
    GemmCtx g;
    g.sb = smem_u32(gsm);
    g.lane = tid & 31;
    const int wid = tid >> 5;
    g.warpM = wid & 3;
    g.warpN = wid >> 2;
    g.mBase = blockIdx.y * GBM;
    g.nBase = blockIdx.x * GBN;

    float acc[2][8][4];
    #pragma unroll
    for (int a = 0; a < 2; a++)
        #pragma unroll
        for (int b = 0; b < 8; b++)
            #pragma unroll
            for (int c2 = 0; c2 < 4; c2++) acc[a][b][c2] = 0.f;

    gemm_mainloop(g, Afg, Bhg, Blg, K, tid, acc);

    const int qrow = g.lane >> 2;
    const int qcol = (g.lane & 3) * 2;
    #pragma unroll
    for (int mt = 0; mt < 2; mt++) {
        const int m0 = g.mBase + g.warpM * 32 + mt * 16 + qrow;
        #pragma unroll
        for (int n8 = 0; n8 < 8; n8++) {
            const int col = g.nBase + g.warpN * 64 + n8 * 8 + qcol;
            float2 v0, v1;
            v0.x = acc[mt][n8][0]; v0.y = acc[mt][n8][1];
            v1.x = acc[mt][n8][2]; v1.y = acc[mt][n8][3];
            const float b0 = bias[col], b1 = bias[col + 1];
            v0.x += b0; v0.y += b1;
            v1.x += b0; v1.y += b1;
            *(float2*)&C[(size_t)m0 * Ntot + col] = v0;
            *(float2*)&C[(size_t)(m0 + 8) * Ntot + col] = v1;
        }
    }
}

// --------------- flash attention (mma.sync fp16, 3-stage KV ring) ---------
#define RSTRIDE 144               // padded smem row (72 fp16)
#define ASQ  0                    // Q region: 128 * 144 = 18432
#define KVB  18432                // KV ring base (3 buffers)
#define KVSZ 36864                // one KV buffer (KH,KL,VH,VL @ 9216 each)
#define KOFF_KL 9216
#define KOFF_VH 18432
#define KOFF_VL 27648
#define ATT_SMEM (KVB + 3 * KVSZ) // 129024

__global__ __launch_bounds__(256, 1)
void flash_attn(const __half* __restrict__ Qfg,
                const __half* __restrict__ Khg, const __half* __restrict__ Klg,
                const __half* __restrict__ Vhg, const __half* __restrict__ Vlg,
                __half* __restrict__ Of)
{
    extern __shared__ char smem[];
    const uint32_t sb = smem_u32(smem);
    const int tid = threadIdx.x, wid = tid >> 5, lane = tid & 31;
    const int qt = (LL / 128 - 1) - blockIdx.x;     // big tiles first
    const int bh = blockIdx.y;
    const int b = bh >> 4, h = bh & 15;
    const int q0 = qt * 128;
    const size_t base = (size_t)bh * LL * HD;

    const int ntiles = q0 / 64 + 2;

    auto stage_kv = [&](int t, int buf) {
        const int k0 = t * 64;
        const uint32_t bo = KVB + buf * KVSZ;
        #pragma unroll
        for (int j = 0; j < 2; j++) {
            const int item = j * 256 + tid;
            const int row = item >> 3, seg = item & 7;
            const size_t g = base + (size_t)(k0 + row) * HD + seg * 8;
            const uint32_t so = bo + row * RSTRIDE + seg * 16;
            cpa16(sb + so,            Khg + g);
            cpa16(sb + so + KOFF_KL,  Klg + g);
            cpa16(sb + so + KOFF_VH,  Vhg + g);
            cpa16(sb + so + KOFF_VL,  Vlg + g);
        }
    };

    // ---- group 0: Q tile + KV tile 0; group 1: KV tile 1 ----
    {
        const int row = tid >> 1, seg = tid & 1;
        const size_t g = base + (size_t)(q0 + row) * HD + seg * 32;
        const uint32_t dq = sb + ASQ + row * RSTRIDE + seg * 64;
        #pragma unroll
        for (int i = 0; i < 4; i++)
            cpa16(dq + i * 16, Qfg + g + i * 8);
    }
    stage_kv(0, 0);
    CP_COMMIT();
    if (ntiles > 1) { stage_kv(1, 1); CP_COMMIT(); CP_WAIT1(); }
    else            { CP_WAIT0(); }
    __syncthreads();

    // ---- Q fragments (persistent; region never overwritten) ----
    uint32_t qf[4][4];
    {
        const uint32_t ro = (wid * 16 + (lane & 15)) * RSTRIDE + ((lane >> 4) << 4);
        #pragma unroll
        for (int ks = 0; ks < 4; ks++)
            ldsm4(qf[ks], sb + ASQ + ro + ks * 32);
    }

    float acc_o[8][4];
    #pragma unroll
    for (int j = 0; j < 8; j++)
        #pragma unroll
        for (int e = 0; e < 4; e++) acc_o[j][e] = 0.f;
    float m0 = -1e30f, m1 = -1e30f, l0 = 0.f, l1 = 0.f;

    const int qmin = q0 + wid * 16;
    const int r_lo = qmin + (lane >> 2);

    for (int t = 0; t < ntiles; t++) {
        const int k0 = t * 64;
        if (t > 0) {
            if (t + 1 < ntiles) { CP_WAIT1(); } else { CP_WAIT0(); }
            __syncthreads();
        }

        if (k0 <= qmin + 15) {                     // not fully masked for this warp
            const uint32_t kb = sb + KVB + (t % 3) * KVSZ;

            // ---- S = Q·(Kh+Kl)ᵀ ----
            float s[8][4];
            #pragma unroll
            for (int j = 0; j < 8; j++)
                #pragma unroll
                for (int e = 0; e < 4; e++) s[j][e] = 0.f;

            #pragma unroll
            for (int ks = 0; ks < 4; ks++) {
                #pragma unroll
                for (int np = 0; np < 4; np++) {
                    uint32_t kh[4], kl[4];
                    const uint32_t ro = (np * 16 + (lane & 15)) * RSTRIDE +
                                        ((lane >> 4) << 4) + ks * 32;
                    ldsm4(kh, kb + ro);
                    ldsm4(kl, kb + KOFF_KL + ro);
                    mma_f16(s[2 * np],     qf[ks], kh[0], kh[2]);
                    mma_f16(s[2 * np],     qf[ks], kl[0], kl[2]);
                    mma_f16(s[2 * np + 1], qf[ks], kh[1], kh[3]);
                    mma_f16(s[2 * np + 1], qf[ks], kl[1], kl[3]);
                }
            }

            // ---- causal mask ----
            if (k0 + 63 > qmin) {
                #pragma unroll
                for (int j = 0; j < 8; j++) {
                    const int key = k0 + j * 8 + (lane & 3) * 2;
                    if (key     > r_lo)     s[j][0] = -1e30f;
                    if (key + 1 > r_lo)     s[j][1] = -1e30f;
                    if (key     > r_lo + 8) s[j][2] = -1e30f;
                    if (key + 1 > r_lo + 8) s[j][3] = -1e30f;
                }
            }

            // ---- online softmax (log2 domain) ----
            float rm0 = -1e30f, rm1 = -1e30f;
            #pragma unroll
            for (int j = 0; j < 8; j++) {
                rm0 = fmaxf(rm0, fmaxf(s[j][0], s[j][1]));
                rm1 = fmaxf(rm1, fmaxf(s[j][2], s[j][3]));
            }
            rm0 = fmaxf(rm0, __shfl_xor_sync(0xffffffff, rm0, 1));
            rm0 = fmaxf(rm0, __shfl_xor_sync(0xffffffff, rm0, 2));
            rm1 = fmaxf(rm1, __shfl_xor_sync(0xffffffff, rm1, 1));
            rm1 = fmaxf(rm1, __shfl_xor_sync(0xffffffff, rm1, 2));

            const float mn0 = fmaxf(m0, rm0), mn1 = fmaxf(m1, rm1);
            const float c0 = fexp2(m0 - mn0), c1 = fexp2(m1 - mn1);
            m0 = mn0; m1 = mn1;
            l0 *= c0; l1 *= c1;
            #pragma unroll
            for (int j = 0; j < 8; j++) {
                acc_o[j][0] *= c0; acc_o[j][1] *= c0;
                acc_o[j][2] *= c1; acc_o[j][3] *= c1;
            }

            float p[8][4];
            #pragma unroll
            for (int j = 0; j < 8; j++) {
                p[j][0] = fexp2(s[j][0] - m0);
                p[j][1] = fexp2(s[j][1] - m0);
                p[j][2] = fexp2(s[j][2] - m1);
                p[j][3] = fexp2(s[j][3] - m1);
                l0 += p[j][0] + p[j][1];
                l1 += p[j][2] + p[j][3];
            }

            // ---- pack P (single fp16) ----
            uint32_t pf[4][4];
            #pragma unroll
            for (int ks = 0; ks < 4; ks++) {
                const int j0 = 2 * ks, j1 = 2 * ks + 1;
                pf[ks][0] = pack2h(p[j0][0], p[j0][1]);
                pf[ks][1] = pack2h(p[j0][2], p[j0][3]);
                pf[ks][2] = pack2h(p[j1][0], p[j1][1]);
                pf[ks][3] = pack2h(p[j1][2], p[j1][3]);
            }

            // ---- O += P·(Vh+Vl) ----
            #pragma unroll
            for (int ks = 0; ks < 4; ks++) {
                #pragma unroll
                for (int np = 0; np < 4; np++) {
                    uint32_t vh[4], vl[4];
                    const int g = lane >> 3;
                    const uint32_t vrow = ks * 16 + (g & 1) * 8 + (lane & 7);
                    const uint32_t ro = vrow * RSTRIDE + np * 32 + (g >> 1) * 16;
                    ldsm4t(vh, kb + KOFF_VH + ro);
                    ldsm4t(vl, kb + KOFF_VL + ro);
                    mma_f16(acc_o[2 * np],     pf[ks], vh[0], vh[1]);
                    mma_f16(acc_o[2 * np],     pf[ks], vl[0], vl[1]);
                    mma_f16(acc_o[2 * np + 1], pf[ks], vh[2], vh[3]);
                    mma_f16(acc_o[2 * np + 1], pf[ks], vl[2], vl[3]);
                }
            }
        }

        if (t + 2 < ntiles) { stage_kv(t + 2, (t + 2) % 3); CP_COMMIT(); }
    }

    // ---- epilogue: normalize, write single fp16 [B*L, 1024] ----
    l0 += __shfl_xor_sync(0xffffffff, l0, 1);
    l0 += __shfl_xor_sync(0xffffffff, l0, 2);
    l1 += __shfl_xor_sync(0xffffffff, l1, 1);
    l1 += __shfl_xor_sync(0xffffffff, l1, 2);
    const float inv0 = 1.0f / l0, inv1 = 1.0f / l1;

    const size_t row0 = (size_t)(b * LL + q0 + wid * 16 + (lane >> 2));
    const size_t row1 = row0 + 8;
    const int colbase = h * HD + (lane & 3) * 2;
    #pragma unroll
    for (int j = 0; j < 8; j++) {
        const int col = colbase + j * 8;
        *(uint32_t*)(Of + row0 * DD + col) = pack2h(acc_o[j][0] * inv0, acc_o[j][1] * inv0);
        *(uint32_t*)(Of + row1 * DD + col) = pack2h(acc_o[j][2] * inv1, acc_o[j][3] * inv1);
    }
}

// -------------------------------------------------------------------------
extern "C" void kernel_launch(void* const* d_in, const int* in_sizes, int n_in,
                              void* d_out, int out_size)
{
    const float* x        = (const float*)d_in[0];
    const float* rope_cos = (const float*)d_in[1];
    const float* rope_sin = (const float*)d_in[2];
    const float* W_qkv    = (const float*)d_in[3];
    const float* W_out    = (const float*)d_in[4];
    const float* b_out    = (const float*)d_in[5];
    float* out = (float*)d_out;

    __half *xf, *wqh, *wql, *woh, *wol, *attf;
    __half *Qf, *Kh, *Kl, *Vh, *Vl;
    cudaGetSymbolAddress((void**)&xf,   g_xf);
    cudaGetSymbolAddress((void**)&wqh,  g_wqkvT_h);
    cudaGetSymbolAddress((void**)&wql,  g_wqkvT_l);
    cudaGetSymbolAddress((void**)&woh,  g_woutT_h);
    cudaGetSymbolAddress((void**)&wol,  g_woutT_l);
    cudaGetSymbolAddress((void**)&attf, g_attf);
    cudaGetSymbolAddress((void**)&Qf,   g_Qf);
    cudaGetSymbolAddress((void**)&Kh,   g_Kh);
    cudaGetSymbolAddress((void**)&Kl,   g_Kl);
    cudaGetSymbolAddress((void**)&Vh,   g_Vh);
    cudaGetSymbolAddress((void**)&Vl,   g_Vl);

    cudaFuncSetAttribute(flash_attn,    cudaFuncAttributeMaxDynamicSharedMemorySize, ATT_SMEM);
    cudaFuncSetAttribute(mma_gemm_qkv,  cudaFuncAttributeMaxDynamicSharedMemorySize, GEMM_SMEM);
    cudaFuncSetAttribute(mma_gemm_bias, cudaFuncAttributeMaxDynamicSharedMemorySize, GEMM_SMEM);

    // 0) operand conversion
    conv_half<<<(MROWS * DD / 4 + 255) / 256, 256>>>(x, xf, MROWS * DD / 4);
    conv_splitT<<<dim3(NQKV / 32, DD / 32), dim3(32, 8)>>>(W_qkv, wqh, wql, DD, NQKV);
    conv_splitT<<<dim3(DD / 32, DD / 32),   dim3(32, 8)>>>(W_out, woh, wol, DD, DD);

    // 1) QKV projection + fused RoPE/split epilogue -> Q/K/V fp16 [B,H,L,HD]
    mma_gemm_qkv<<<dim3(NQKV / GBN, MROWS / GBM), 256, GEMM_SMEM>>>(
        xf, wqh, wql, rope_cos, rope_sin, Qf, Kh, Kl, Vh, Vl);

    // 2) flash attention (fp16 tensor cores, 3-stage KV ring) -> fp16
    flash_attn<<<dim3(LL / 128, BB * HH), 256, ATT_SMEM>>>(
        Qf, Kh, Kl, Vh, Vl, attf);

    // 3) output projection + bias (fp16 2-term)
    mma_gemm_bias<<<dim3(DD / GBN, MROWS / GBM), 256, GEMM_SMEM>>>(
        attf, woh, wol, b_out, out, DD, DD);
}